// round 5
// baseline (speedup 1.0000x reference)
#include <cuda_runtime.h>
#include <math.h>

// Problem constants
#define B_   128
#define T_   200
#define TM1  199
#define NQP1 5001
#define NTOK  (B_ * T_)    // 25600
#define NTOK1 (B_ * TM1)   // 25472

// ---------------------------------------------------------------------------
// Device scratch (static __device__ arrays: no allocation in kernel_launch)
// ---------------------------------------------------------------------------
__device__ __align__(16) float g_qa    [NTOK  * 256];  // [qe | ae] per token
__device__ __align__(16) float g_t1    [NTOK  * 128];  // qa @ We.T + be
__device__ __align__(16) float g_t2    [NTOK  * 128];  // qa @ Wa.T + ba
__device__ __align__(16) float g_rk    [NTOK  * 128];  // qe @ Wk.T + bk
__device__ __align__(16) float g_logits[NTOK  *  64];
__device__ __align__(16) float g_corr  [NTOK  *  64];
__device__ __align__(16) float g_erase [NTOK  * 128];
__device__ __align__(16) float g_add   [NTOK  * 128];
__device__ __align__(16) float g_rc    [NTOK1 * 128];
__device__ __align__(16) float g_rcn   [NTOK1 * 128];
__device__ __align__(16) float g_beh   [NTOK1 * 256];
__device__ __align__(16) float g_mas   [NTOK1 * 256];
__device__ __align__(16) float g_hb    [NTOK1 * 256];
__device__ __align__(16) float g_hs    [NTOK1 * 256];

// ---------------------------------------------------------------------------
// Generic fp32 GEMM:  C[m,n] = act( sum_k A[m,k] * W[n,k] + bias[n] )
// Both operands K-major (row-major A: MxK, row-major W: NxK) -> "NT" gemm.
// Tiles: 128x128x8, 256 threads, 8x8 per-thread microtile.
// ACT: 0 = none, 1 = sigmoid, 2 = tanh
// Requires: M multiple of 128 (true for all call sites: 25600, 25472),
//           K multiple of 8, lda/ldw multiple of 4. N arbitrary (guarded).
// ---------------------------------------------------------------------------
template <int ACT>
__global__ void __launch_bounds__(256, 2) gemm_nt_kernel(
    const float* __restrict__ A, int lda,
    const float* __restrict__ W, int ldw,
    const float* __restrict__ bias,
    float* __restrict__ C, int ldc,
    int M, int N, int K)
{
    __shared__ float As[8][132];
    __shared__ float Bs[8][132];

    const int tid = threadIdx.x;
    const int m0  = blockIdx.y * 128;
    const int n0  = blockIdx.x * 128;
    const int tx  = tid & 15;        // 0..15  -> n micro-tile
    const int ty  = tid >> 4;        // 0..15  -> m micro-tile
    const int lr  = tid >> 1;        // 0..127 load row
    const int lc  = (tid & 1) << 2;  // 0 or 4 load col (float4)

    float acc[8][8];
#pragma unroll
    for (int i = 0; i < 8; i++)
#pragma unroll
        for (int j = 0; j < 8; j++) acc[i][j] = 0.f;

    const float* Ap = A + (size_t)(m0 + lr) * lda + lc;
    const int    wrow = n0 + lr;
    const float* Wp = W + (size_t)wrow * ldw + lc;
    const bool   wok = (wrow < N);

    for (int k0 = 0; k0 < K; k0 += 8) {
        float4 av = *reinterpret_cast<const float4*>(Ap + k0);
        float4 wv = wok ? *reinterpret_cast<const float4*>(Wp + k0)
                        : make_float4(0.f, 0.f, 0.f, 0.f);
        __syncthreads();
        As[lc + 0][lr] = av.x; As[lc + 1][lr] = av.y;
        As[lc + 2][lr] = av.z; As[lc + 3][lr] = av.w;
        Bs[lc + 0][lr] = wv.x; Bs[lc + 1][lr] = wv.y;
        Bs[lc + 2][lr] = wv.z; Bs[lc + 3][lr] = wv.w;
        __syncthreads();
#pragma unroll
        for (int kk = 0; kk < 8; kk++) {
            float4 a0 = *reinterpret_cast<const float4*>(&As[kk][ty * 8]);
            float4 a1 = *reinterpret_cast<const float4*>(&As[kk][ty * 8 + 4]);
            float4 b0 = *reinterpret_cast<const float4*>(&Bs[kk][tx * 8]);
            float4 b1 = *reinterpret_cast<const float4*>(&Bs[kk][tx * 8 + 4]);
            float a[8] = {a0.x, a0.y, a0.z, a0.w, a1.x, a1.y, a1.z, a1.w};
            float b[8] = {b0.x, b0.y, b0.z, b0.w, b1.x, b1.y, b1.z, b1.w};
#pragma unroll
            for (int i = 0; i < 8; i++)
#pragma unroll
                for (int j = 0; j < 8; j++)
                    acc[i][j] = fmaf(a[i], b[j], acc[i][j]);
        }
    }

    float bb[8];
#pragma unroll
    for (int j = 0; j < 8; j++) {
        int n = n0 + tx * 8 + j;
        bb[j] = (bias != nullptr && n < N) ? bias[n] : 0.f;
    }
#pragma unroll
    for (int i = 0; i < 8; i++) {
        int m = m0 + ty * 8 + i;
        if (m >= M) continue;
#pragma unroll
        for (int j = 0; j < 8; j++) {
            int n = n0 + tx * 8 + j;
            if (n >= N) continue;
            float v = acc[i][j] + bb[j];
            if (ACT == 1) v = 1.f / (1.f + __expf(-v));
            else if (ACT == 2) v = tanhf(v);
            C[(size_t)m * ldc + n] = v;
        }
    }
}

// ---------------------------------------------------------------------------
// Gather: qa[token] = [q_embed[q_data[token]] | a_embed[a_data[token]]]
// ---------------------------------------------------------------------------
__global__ void gather_kernel(const int* __restrict__ q, const int* __restrict__ a,
                              const float* __restrict__ qe, const float* __restrict__ ae,
                              float* __restrict__ qa)
{
    int tok = blockIdx.x;
    int i   = threadIdx.x;                 // 0..255
    int qi  = q[tok];
    int ai  = a[tok];
    float v = (i < 128) ? qe[(size_t)qi * 128 + i]
                        : ae[(size_t)ai * 128 + (i - 128)];
    qa[(size_t)tok * 256 + i] = v;
}

// ---------------------------------------------------------------------------
// Softmax over 64 logits, one warp per token
// ---------------------------------------------------------------------------
__global__ void softmax64_kernel(const float* __restrict__ lg, float* __restrict__ co,
                                 int ntok)
{
    int g    = blockIdx.x * blockDim.x + threadIdx.x;
    int w    = g >> 5;
    int lane = g & 31;
    if (w >= ntok) return;
    const float* L = lg + (size_t)w * 64;
    float v0 = L[lane], v1 = L[lane + 32];
    float mx = fmaxf(v0, v1);
#pragma unroll
    for (int o = 16; o; o >>= 1) mx = fmaxf(mx, __shfl_xor_sync(0xffffffffu, mx, o));
    float e0 = __expf(v0 - mx), e1 = __expf(v1 - mx);
    float s = e0 + e1;
#pragma unroll
    for (int o = 16; o; o >>= 1) s += __shfl_xor_sync(0xffffffffu, s, o);
    float inv = 1.f / s;
    co[(size_t)w * 64 + lane]      = e0 * inv;
    co[(size_t)w * 64 + lane + 32] = e1 * inv;
}

// ---------------------------------------------------------------------------
// Sequential memory scan. One CTA per batch; M[64][128] in registers
// (256 threads: thread owns column v = tid&127 for 32 c-rows, cg = tid>>7).
// ---------------------------------------------------------------------------
__global__ void __launch_bounds__(256) scan_kernel(
    const float* __restrict__ corr, const float* __restrict__ er,
    const float* __restrict__ ad,   const float* __restrict__ vinit,
    float* __restrict__ rc, float* __restrict__ rcn)
{
    int b   = blockIdx.x;
    int tid = threadIdx.x;
    int v   = tid & 127;
    int cg  = tid >> 7;   // 0 or 1

    float M[32];
#pragma unroll
    for (int i = 0; i < 32; i++) M[i] = vinit[(size_t)(cg * 32 + i) * 128 + v];

    __shared__ float sw[64], swn[64], s_rc[128], s_rcn[128];

    const float* corr_b = corr + (size_t)b * T_ * 64;
    const float* er_b   = er   + (size_t)b * T_ * 128;
    const float* ad_b   = ad   + (size_t)b * T_ * 128;
    float* rc_b  = rc  + (size_t)b * TM1 * 128;
    float* rcn_b = rcn + (size_t)b * TM1 * 128;

    float ev_n = er_b[v];
    float av_n = ad_b[v];

    for (int t = 0; t < TM1; t++) {
        float ev = ev_n, av = av_n;
        if (t + 1 < TM1) {   // prefetch next step's erase/add
            ev_n = er_b[(size_t)(t + 1) * 128 + v];
            av_n = ad_b[(size_t)(t + 1) * 128 + v];
        }
        if (tid < 64)       sw[tid]       = corr_b[(size_t)t * 64 + tid];
        else if (tid < 128) swn[tid - 64] = corr_b[(size_t)(t + 1) * 64 + (tid - 64)];
        __syncthreads();

        float prc = 0.f, prcn = 0.f;
#pragma unroll
        for (int i = 0; i < 32; i++) {
            float wc = sw[cg * 32 + i];
            float m  = fmaf(wc, av, M[i] * (1.f - wc * ev));
            M[i] = m;
            prc  = fmaf(wc, m, prc);
            prcn = fmaf(swn[cg * 32 + i], m, prcn);
        }
        if (cg == 0) { s_rc[v] = prc; s_rcn[v] = prcn; }
        __syncthreads();
        if (cg == 1) {
            rc_b [(size_t)t * 128 + v] = s_rc[v]  + prc;
            rcn_b[(size_t)t * 128 + v] = s_rcn[v] + prcn;
        }
        __syncthreads();  // protect sw/s_rc before next iteration's writes
    }
}

// ---------------------------------------------------------------------------
// behavior = [rc, qe[:, :T-1]] ; mastery = [rc_next, qe[:, 1:]]
// ---------------------------------------------------------------------------
__global__ void behmas_kernel(const float* __restrict__ rc, const float* __restrict__ rcn,
                              const float* __restrict__ qa,
                              float* __restrict__ beh, float* __restrict__ mas)
{
    int tok = blockIdx.x;          // 0..NTOK1-1 (= b*199 + t)
    int i   = threadIdx.x;         // 0..255
    int b   = tok / TM1;
    int t   = tok - b * TM1;
    size_t o = (size_t)tok * 256 + i;
    if (i < 128) {
        beh[o] = rc [(size_t)tok * 128 + i];
        mas[o] = rcn[(size_t)tok * 128 + i];
    } else {
        beh[o] = qa[(size_t)(b * T_ + t)     * 256 + (i - 128)];
        mas[o] = qa[(size_t)(b * T_ + t + 1) * 256 + (i - 128)];
    }
}

// ---------------------------------------------------------------------------
// pred = sigmoid(hs . Wo + bo), one warp per token
// ---------------------------------------------------------------------------
__global__ void pred_kernel(const float* __restrict__ hs, const float* __restrict__ Wo,
                            const float* __restrict__ bo, float* __restrict__ out, int ntok)
{
    int g    = blockIdx.x * blockDim.x + threadIdx.x;
    int w    = g >> 5;
    int lane = g & 31;
    if (w >= ntok) return;
    const float* h = hs + (size_t)w * 256;
    float s = 0.f;
#pragma unroll
    for (int j = 0; j < 8; j++) s = fmaf(h[lane + j * 32], Wo[lane + j * 32], s);
#pragma unroll
    for (int o = 16; o; o >>= 1) s += __shfl_xor_sync(0xffffffffu, s, o);
    if (lane == 0) out[w] = 1.f / (1.f + __expf(-(s + bo[0])));
}

// ---------------------------------------------------------------------------
// Launch
// ---------------------------------------------------------------------------
extern "C" void kernel_launch(void* const* d_in, const int* in_sizes, int n_in,
                              void* d_out, int out_size)
{
    (void)in_sizes; (void)n_in; (void)out_size;

    const int*   q_data     = (const int*)  d_in[0];
    const int*   a_data     = (const int*)  d_in[1];
    const float* q_embed    = (const float*)d_in[2];
    const float* a_embed    = (const float*)d_in[3];
    const float* key_matrix = (const float*)d_in[4];
    const float* value_init = (const float*)d_in[5];
    const float* Wk  = (const float*)d_in[6];   const float* bk  = (const float*)d_in[7];
    const float* We  = (const float*)d_in[8];   const float* be  = (const float*)d_in[9];
    const float* We2 = (const float*)d_in[10];  const float* be2 = (const float*)d_in[11];
    const float* Wa  = (const float*)d_in[12];  const float* ba  = (const float*)d_in[13];
    const float* Wa2 = (const float*)d_in[14];  const float* ba2 = (const float*)d_in[15];
    const float* Ws  = (const float*)d_in[16];  const float* bs  = (const float*)d_in[17];
    const float* Wo  = (const float*)d_in[18];  const float* bo  = (const float*)d_in[19];
    const float* Wsb = (const float*)d_in[20];  const float* bsb = (const float*)d_in[21];
    const float* Wob = (const float*)d_in[22];  const float* bob = (const float*)d_in[23];
    float* out = (float*)d_out;

    float *p_qa, *p_t1, *p_t2, *p_rk, *p_log, *p_corr, *p_er, *p_ad;
    float *p_rc, *p_rcn, *p_beh, *p_mas, *p_hb, *p_hs;
    cudaGetSymbolAddress((void**)&p_qa,   g_qa);
    cudaGetSymbolAddress((void**)&p_t1,   g_t1);
    cudaGetSymbolAddress((void**)&p_t2,   g_t2);
    cudaGetSymbolAddress((void**)&p_rk,   g_rk);
    cudaGetSymbolAddress((void**)&p_log,  g_logits);
    cudaGetSymbolAddress((void**)&p_corr, g_corr);
    cudaGetSymbolAddress((void**)&p_er,   g_erase);
    cudaGetSymbolAddress((void**)&p_ad,   g_add);
    cudaGetSymbolAddress((void**)&p_rc,   g_rc);
    cudaGetSymbolAddress((void**)&p_rcn,  g_rcn);
    cudaGetSymbolAddress((void**)&p_beh,  g_beh);
    cudaGetSymbolAddress((void**)&p_mas,  g_mas);
    cudaGetSymbolAddress((void**)&p_hb,   g_hb);
    cudaGetSymbolAddress((void**)&p_hs,   g_hs);

    const dim3 blk(256);

    // Stage 0: gathers
    gather_kernel<<<NTOK, 256>>>(q_data, a_data, q_embed, a_embed, p_qa);

    // Stage A: token-wise feature GEMMs (M = 25600, multiple of 128)
    gemm_nt_kernel<0><<<dim3(1, NTOK / 128), blk>>>(p_qa, 256, We,  256, be,  p_t1, 128, NTOK, 128, 256);
    gemm_nt_kernel<0><<<dim3(1, NTOK / 128), blk>>>(p_qa, 256, Wa,  256, ba,  p_t2, 128, NTOK, 128, 256);
    gemm_nt_kernel<0><<<dim3(1, NTOK / 128), blk>>>(p_qa, 256, Wk,  128, bk,  p_rk, 128, NTOK, 128, 128);
    gemm_nt_kernel<1><<<dim3(1, NTOK / 128), blk>>>(p_t1, 128, We2, 128, be2, p_er, 128, NTOK, 128, 128);
    gemm_nt_kernel<2><<<dim3(1, NTOK / 128), blk>>>(p_t2, 128, Wa2, 128, ba2, p_ad, 128, NTOK, 128, 128);
    gemm_nt_kernel<0><<<dim3(1, NTOK / 128), blk>>>(p_rk, 128, key_matrix, 128, nullptr, p_log, 64, NTOK, 64, 128);
    softmax64_kernel<<<(NTOK * 32 + 255) / 256, 256>>>(p_log, p_corr, NTOK);

    // Stage B: sequential memory scan (one CTA per batch)
    scan_kernel<<<B_, 256>>>(p_corr, p_er, p_ad, value_init, p_rc, p_rcn);

    // Stage C: readout
    behmas_kernel<<<NTOK1, 256>>>(p_rc, p_rcn, p_qa, p_beh, p_mas);
    gemm_nt_kernel<2><<<dim3(2, NTOK1 / 128), blk>>>(p_beh, 256, Wsb, 256, bsb, p_hb, 256, NTOK1, 256, 256);
    gemm_nt_kernel<2><<<dim3(2, NTOK1 / 128), blk>>>(p_mas, 256, Ws,  256, bs,  p_hs, 256, NTOK1, 256, 256);
    pred_kernel<<<(NTOK1 * 32 + 255) / 256, 256>>>(p_hs, Wo, bo, out, NTOK1);

    // The big one: pred_material = sigmoid(hb @ Wob.T + bob), 25472 x 5001, K=256
    gemm_nt_kernel<1><<<dim3((NQP1 + 127) / 128, NTOK1 / 128), blk>>>(
        p_hb, 256, Wob, 256, bob, out + NTOK1, NQP1, NTOK1, NQP1, 256);
}

// round 7
// speedup vs baseline: 1.6759x; 1.6759x over previous
#include <cuda_runtime.h>
#include <cuda_bf16.h>
#include <math.h>

// Problem constants
#define B_   128
#define T_   200
#define TM1  199
#define NQP1 5001
#define NPAD 5120            // 5001 padded to 40*128 tiles
#define K3   768             // 3 * 256 (bf16 hi/lo split GEMM)
#define NTOK  (B_ * T_)      // 25600
#define NTOK1 (B_ * TM1)     // 25472

// ---------------------------------------------------------------------------
// Device scratch
// ---------------------------------------------------------------------------
__device__ __align__(16) float g_qa    [NTOK  * 256];
__device__ __align__(16) float g_t1    [NTOK  * 128];
__device__ __align__(16) float g_t2    [NTOK  * 128];
__device__ __align__(16) float g_rk    [NTOK  * 128];
__device__ __align__(16) float g_logits[NTOK  *  64];
__device__ __align__(16) float g_corr  [NTOK  *  64];
__device__ __align__(16) float g_erase [NTOK  * 128];
__device__ __align__(16) float g_add   [NTOK  * 128];
__device__ __align__(16) float g_rc    [NTOK1 * 128];
__device__ __align__(16) float g_rcn   [NTOK1 * 128];
__device__ __align__(16) float g_beh   [NTOK1 * 256];
__device__ __align__(16) float g_mas   [NTOK1 * 256];
__device__ __align__(16) float g_hb    [NTOK1 * 256];
__device__ __align__(16) float g_hs    [NTOK1 * 256];
__device__ __align__(16) __nv_bfloat16 g_A3[(size_t)NTOK1 * K3];  // hb split
__device__ __align__(16) __nv_bfloat16 g_B3[(size_t)NPAD  * K3];  // Wob split

// ---------------------------------------------------------------------------
// fp32 SIMT GEMM body: C[m,n] = act(sum_k A[m,k]*W[n,k] + bias[n])
// 128x128x8 tiles, 256 threads, 8x8 microtile. act: 0 none, 1 sigmoid, 2 tanh
// ---------------------------------------------------------------------------
__device__ __forceinline__ void gemm_body(
    const float* __restrict__ A, int lda,
    const float* __restrict__ W, int ldw,
    const float* __restrict__ bias,
    float* __restrict__ C, int ldc,
    int M, int N, int K, int act,
    int m0, int n0)
{
    __shared__ float As[8][132];
    __shared__ float Bs[8][132];

    const int tid = threadIdx.x;
    const int tx  = tid & 15;
    const int ty  = tid >> 4;
    const int lr  = tid >> 1;
    const int lc  = (tid & 1) << 2;

    float acc[8][8];
#pragma unroll
    for (int i = 0; i < 8; i++)
#pragma unroll
        for (int j = 0; j < 8; j++) acc[i][j] = 0.f;

    const float* Ap = A + (size_t)(m0 + lr) * lda + lc;
    const int    wrow = n0 + lr;
    const float* Wp = W + (size_t)wrow * ldw + lc;
    const bool   wok = (wrow < N);

    for (int k0 = 0; k0 < K; k0 += 8) {
        float4 av = *reinterpret_cast<const float4*>(Ap + k0);
        float4 wv = wok ? *reinterpret_cast<const float4*>(Wp + k0)
                        : make_float4(0.f, 0.f, 0.f, 0.f);
        __syncthreads();
        As[lc + 0][lr] = av.x; As[lc + 1][lr] = av.y;
        As[lc + 2][lr] = av.z; As[lc + 3][lr] = av.w;
        Bs[lc + 0][lr] = wv.x; Bs[lc + 1][lr] = wv.y;
        Bs[lc + 2][lr] = wv.z; Bs[lc + 3][lr] = wv.w;
        __syncthreads();
#pragma unroll
        for (int kk = 0; kk < 8; kk++) {
            float4 a0 = *reinterpret_cast<const float4*>(&As[kk][ty * 8]);
            float4 a1 = *reinterpret_cast<const float4*>(&As[kk][ty * 8 + 4]);
            float4 b0 = *reinterpret_cast<const float4*>(&Bs[kk][tx * 8]);
            float4 b1 = *reinterpret_cast<const float4*>(&Bs[kk][tx * 8 + 4]);
            float a[8] = {a0.x, a0.y, a0.z, a0.w, a1.x, a1.y, a1.z, a1.w};
            float b[8] = {b0.x, b0.y, b0.z, b0.w, b1.x, b1.y, b1.z, b1.w};
#pragma unroll
            for (int i = 0; i < 8; i++)
#pragma unroll
                for (int j = 0; j < 8; j++)
                    acc[i][j] = fmaf(a[i], b[j], acc[i][j]);
        }
    }

    float bb[8];
#pragma unroll
    for (int j = 0; j < 8; j++) {
        int n = n0 + tx * 8 + j;
        bb[j] = (bias != nullptr && n < N) ? bias[n] : 0.f;
    }
#pragma unroll
    for (int i = 0; i < 8; i++) {
        int m = m0 + ty * 8 + i;
        if (m >= M) continue;
#pragma unroll
        for (int j = 0; j < 8; j++) {
            int n = n0 + tx * 8 + j;
            if (n >= N) continue;
            float v = acc[i][j] + bb[j];
            if (act == 1) v = 1.f / (1.f + __expf(-v));
            else if (act == 2) v = tanhf(v);
            C[(size_t)m * ldc + n] = v;
        }
    }
}

__global__ void __launch_bounds__(256, 2) gemm_nt_kernel(
    const float* __restrict__ A, int lda,
    const float* __restrict__ W, int ldw,
    const float* __restrict__ bias,
    float* __restrict__ C, int ldc,
    int M, int N, int K, int act)
{
    gemm_body(A, lda, W, ldw, bias, C, ldc, M, N, K, act,
              blockIdx.y * 128, blockIdx.x * 128);
}

// Fused: z=0 -> t1 = qa@We.T+be (K=256, ldw=256)
//        z=1 -> t2 = qa@Wa.T+ba (K=256, ldw=256)
//        z=2 -> rk = qe@Wk.T+bk (K=128, ldw=128 !!)  qe = first 128 cols of qa
__global__ void __launch_bounds__(256, 2) gemm_fused3_kernel(
    const float* __restrict__ qa,
    const float* __restrict__ We, const float* __restrict__ be,
    const float* __restrict__ Wa, const float* __restrict__ ba,
    const float* __restrict__ Wk, const float* __restrict__ bk,
    float* __restrict__ t1, float* __restrict__ t2, float* __restrict__ rk)
{
    const float* W; const float* bias; float* C; int K; int ldw;
    if (blockIdx.z == 0)      { W = We; bias = be; C = t1; K = 256; ldw = 256; }
    else if (blockIdx.z == 1) { W = Wa; bias = ba; C = t2; K = 256; ldw = 256; }
    else                      { W = Wk; bias = bk; C = rk; K = 128; ldw = 128; }
    gemm_body(qa, 256, W, ldw, bias, C, 128, NTOK, 128, K, 0,
              blockIdx.y * 128, 0);
}

// Fused: z=0 -> er = sigmoid(t1@We2.T+be2); z=1 -> ad = tanh(t2@Wa2.T+ba2)
__global__ void __launch_bounds__(256, 2) gemm_fused2_kernel(
    const float* __restrict__ t1, const float* __restrict__ t2,
    const float* __restrict__ We2, const float* __restrict__ be2,
    const float* __restrict__ Wa2, const float* __restrict__ ba2,
    float* __restrict__ er, float* __restrict__ ad)
{
    const float* A; const float* W; const float* bias; float* C; int act;
    if (blockIdx.z == 0) { A = t1; W = We2; bias = be2; C = er; act = 1; }
    else                 { A = t2; W = Wa2; bias = ba2; C = ad; act = 2; }
    gemm_body(A, 128, W, 128, bias, C, 128, NTOK, 128, 128, act,
              blockIdx.y * 128, 0);
}

// ---------------------------------------------------------------------------
// bf16 hi/lo split conversions
// A3 = [hi(hb) | lo(hb) | hi(hb)]   (per row, K 256 each)
// B3 = [hi(Wob)| hi(Wob)| lo(Wob)]  (rows >= 5001 zeroed)
// Dropped term Al*Bl ~ 2^-16 relative: well under 1e-3 threshold.
// ---------------------------------------------------------------------------
__global__ void convA_kernel(const float* __restrict__ X, __nv_bfloat16* __restrict__ Y)
{
    int idx = blockIdx.x * 256 + threadIdx.x;     // < NTOK1*256
    int r = idx >> 8, c = idx & 255;
    float x = X[idx];
    __nv_bfloat16 h = __float2bfloat16(x);
    __nv_bfloat16 l = __float2bfloat16(x - __bfloat162float(h));
    size_t base = (size_t)r * K3;
    Y[base + c] = h; Y[base + 256 + c] = l; Y[base + 512 + c] = h;
}

__global__ void convB_kernel(const float* __restrict__ X, __nv_bfloat16* __restrict__ Y)
{
    int idx = blockIdx.x * 256 + threadIdx.x;     // < NPAD*256
    int r = idx >> 8, c = idx & 255;
    float x = (r < NQP1) ? X[(size_t)r * 256 + c] : 0.f;
    __nv_bfloat16 h = __float2bfloat16(x);
    __nv_bfloat16 l = __float2bfloat16(x - __bfloat162float(h));
    size_t base = (size_t)r * K3;
    Y[base + c] = h; Y[base + 256 + c] = h; Y[base + 512 + c] = l;
}

// ---------------------------------------------------------------------------
// Big tensor-core GEMM: out = sigmoid(A3[M,768] @ B3[NPAD,768].T + bob)
// mma.sync.m16n8k16 bf16, CTA tile 128x128x32, cp.async double buffer.
// 256 threads = 8 warps (2x4), warp tile 64x32.
// ---------------------------------------------------------------------------
__device__ __forceinline__ void mma16816(float c[4], const unsigned a[4],
                                         unsigned b0, unsigned b1)
{
    asm volatile(
        "mma.sync.aligned.m16n8k16.row.col.f32.bf16.bf16.f32 "
        "{%0,%1,%2,%3}, {%4,%5,%6,%7}, {%8,%9}, {%0,%1,%2,%3};\n"
        : "+f"(c[0]), "+f"(c[1]), "+f"(c[2]), "+f"(c[3])
        : "r"(a[0]), "r"(a[1]), "r"(a[2]), "r"(a[3]), "r"(b0), "r"(b1));
}

__device__ __forceinline__ unsigned saddr(const void* p)
{
    return (unsigned)__cvta_generic_to_shared(p);
}

__device__ __forceinline__ void cp16(unsigned d, const void* s)
{
    asm volatile("cp.async.cg.shared.global [%0], [%1], 16;\n" :: "r"(d), "l"(s));
}

__global__ void __launch_bounds__(256, 2) mma_big_kernel(
    const __nv_bfloat16* __restrict__ A,   // [NTOK1][768]
    const __nv_bfloat16* __restrict__ Bm,  // [NPAD][768]
    const float* __restrict__ bias,        // bob [5001]
    float* __restrict__ C)                 // [NTOK1][5001]
{
    __shared__ __nv_bfloat16 As[2][128][40];   // pitch 40 bf16 = 80B
    __shared__ __nv_bfloat16 Bs[2][128][40];

    const int tid  = threadIdx.x;
    const int lane = tid & 31, wid = tid >> 5;
    const int wm = wid & 1, wn = wid >> 1;       // warp grid 2(M) x 4(N)
    const int m0 = blockIdx.y * 128;
    const int n0 = blockIdx.x * 128;

    float acc[4][4][4];
#pragma unroll
    for (int mt = 0; mt < 4; mt++)
#pragma unroll
        for (int nt = 0; nt < 4; nt++)
#pragma unroll
            for (int r = 0; r < 4; r++) acc[mt][nt][r] = 0.f;

    const __nv_bfloat16* Ag = A  + (size_t)m0 * K3;
    const __nv_bfloat16* Bg = Bm + (size_t)n0 * K3;
    const int rr = tid >> 1;             // row 0..127
    const int s0 = (tid & 1) * 2;        // 2 x 16B = 32B per operand row

    // ldmatrix per-lane address components
    const int lr8 = (lane & 7) + ((lane >> 3) & 1) * 8;
    const int lc8 = (lane >> 4) * 8;

    const int NST = K3 / 32;   // 24 stages

    {
        const __nv_bfloat16* pa = Ag + (size_t)rr * K3 + s0 * 8;
        const __nv_bfloat16* pb = Bg + (size_t)rr * K3 + s0 * 8;
        cp16(saddr(&As[0][rr][s0 * 8]),     pa);
        cp16(saddr(&As[0][rr][s0 * 8 + 8]), pa + 8);
        cp16(saddr(&Bs[0][rr][s0 * 8]),     pb);
        cp16(saddr(&Bs[0][rr][s0 * 8 + 8]), pb + 8);
        asm volatile("cp.async.commit_group;\n");
    }

    for (int st = 0; st < NST; st++) {
        if (st + 1 < NST) {
            int nb = (st + 1) & 1, k0 = (st + 1) * 32;
            const __nv_bfloat16* pa = Ag + (size_t)rr * K3 + k0 + s0 * 8;
            const __nv_bfloat16* pb = Bg + (size_t)rr * K3 + k0 + s0 * 8;
            cp16(saddr(&As[nb][rr][s0 * 8]),     pa);
            cp16(saddr(&As[nb][rr][s0 * 8 + 8]), pa + 8);
            cp16(saddr(&Bs[nb][rr][s0 * 8]),     pb);
            cp16(saddr(&Bs[nb][rr][s0 * 8 + 8]), pb + 8);
            asm volatile("cp.async.commit_group;\n");
            asm volatile("cp.async.wait_group 1;\n");
        } else {
            asm volatile("cp.async.wait_group 0;\n");
        }
        __syncthreads();

        const int buf = st & 1;
#pragma unroll
        for (int ks = 0; ks < 2; ks++) {
            const int kc = ks * 16 + lc8;
            unsigned af[4][4], bq[4][2];
#pragma unroll
            for (int mt = 0; mt < 4; mt++) {
                unsigned ad = saddr(&As[buf][wm * 64 + mt * 16 + lr8][kc]);
                asm volatile(
                    "ldmatrix.sync.aligned.m8n8.x4.shared.b16 {%0,%1,%2,%3}, [%4];\n"
                    : "=r"(af[mt][0]), "=r"(af[mt][1]),
                      "=r"(af[mt][2]), "=r"(af[mt][3]) : "r"(ad));
            }
#pragma unroll
            for (int bh = 0; bh < 2; bh++) {
                unsigned r0, r1, r2, r3;
                unsigned ad = saddr(&Bs[buf][wn * 32 + bh * 16 + lr8][kc]);
                asm volatile(
                    "ldmatrix.sync.aligned.m8n8.x4.shared.b16 {%0,%1,%2,%3}, [%4];\n"
                    : "=r"(r0), "=r"(r1), "=r"(r2), "=r"(r3) : "r"(ad));
                bq[bh * 2 + 0][0] = r0; bq[bh * 2 + 0][1] = r2;
                bq[bh * 2 + 1][0] = r1; bq[bh * 2 + 1][1] = r3;
            }
#pragma unroll
            for (int mt = 0; mt < 4; mt++)
#pragma unroll
                for (int nt = 0; nt < 4; nt++)
                    mma16816(acc[mt][nt], af[mt], bq[nt][0], bq[nt][1]);
        }
        __syncthreads();
    }

    // --- epilogue: bias + sigmoid, guarded at N=5001 ---
    const int gidr = lane >> 2, tig = lane & 3;
#pragma unroll
    for (int nt = 0; nt < 4; nt++) {
        const int n = n0 + wn * 32 + nt * 8 + tig * 2;
        const bool ok0 = (n < NQP1), ok1 = (n + 1 < NQP1);
        const float bb0 = ok0 ? bias[n] : 0.f;
        const float bb1 = ok1 ? bias[n + 1] : 0.f;
#pragma unroll
        for (int mt = 0; mt < 4; mt++) {
            const int m = m0 + wm * 64 + mt * 16 + gidr;
            float* Cr0 = C + (size_t)m * NQP1;
            float* Cr1 = C + (size_t)(m + 8) * NQP1;
            if (ok0) {
                Cr0[n] = 1.f / (1.f + __expf(-(acc[mt][nt][0] + bb0)));
                Cr1[n] = 1.f / (1.f + __expf(-(acc[mt][nt][2] + bb0)));
            }
            if (ok1) {
                Cr0[n + 1] = 1.f / (1.f + __expf(-(acc[mt][nt][1] + bb1)));
                Cr1[n + 1] = 1.f / (1.f + __expf(-(acc[mt][nt][3] + bb1)));
            }
        }
    }
}

// ---------------------------------------------------------------------------
// Gather / softmax / scan / concat / pred (verified round 5)
// ---------------------------------------------------------------------------
__global__ void gather_kernel(const int* __restrict__ q, const int* __restrict__ a,
                              const float* __restrict__ qe, const float* __restrict__ ae,
                              float* __restrict__ qa)
{
    int tok = blockIdx.x;
    int i   = threadIdx.x;
    int qi  = q[tok];
    int ai  = a[tok];
    float v = (i < 128) ? qe[(size_t)qi * 128 + i]
                        : ae[(size_t)ai * 128 + (i - 128)];
    qa[(size_t)tok * 256 + i] = v;
}

__global__ void softmax64_kernel(const float* __restrict__ lg, float* __restrict__ co,
                                 int ntok)
{
    int g    = blockIdx.x * blockDim.x + threadIdx.x;
    int w    = g >> 5;
    int lane = g & 31;
    if (w >= ntok) return;
    const float* L = lg + (size_t)w * 64;
    float v0 = L[lane], v1 = L[lane + 32];
    float mx = fmaxf(v0, v1);
#pragma unroll
    for (int o = 16; o; o >>= 1) mx = fmaxf(mx, __shfl_xor_sync(0xffffffffu, mx, o));
    float e0 = __expf(v0 - mx), e1 = __expf(v1 - mx);
    float s = e0 + e1;
#pragma unroll
    for (int o = 16; o; o >>= 1) s += __shfl_xor_sync(0xffffffffu, s, o);
    float inv = 1.f / s;
    co[(size_t)w * 64 + lane]      = e0 * inv;
    co[(size_t)w * 64 + lane + 32] = e1 * inv;
}

__global__ void __launch_bounds__(256) scan_kernel(
    const float* __restrict__ corr, const float* __restrict__ er,
    const float* __restrict__ ad,   const float* __restrict__ vinit,
    float* __restrict__ rc, float* __restrict__ rcn)
{
    int b   = blockIdx.x;
    int tid = threadIdx.x;
    int v   = tid & 127;
    int cg  = tid >> 7;

    float M[32];
#pragma unroll
    for (int i = 0; i < 32; i++) M[i] = vinit[(size_t)(cg * 32 + i) * 128 + v];

    __shared__ float sw[64], swn[64], s_rc[128], s_rcn[128];

    const float* corr_b = corr + (size_t)b * T_ * 64;
    const float* er_b   = er   + (size_t)b * T_ * 128;
    const float* ad_b   = ad   + (size_t)b * T_ * 128;
    float* rc_b  = rc  + (size_t)b * TM1 * 128;
    float* rcn_b = rcn + (size_t)b * TM1 * 128;

    float ev_n = er_b[v];
    float av_n = ad_b[v];

    for (int t = 0; t < TM1; t++) {
        float ev = ev_n, av = av_n;
        if (t + 1 < TM1) {
            ev_n = er_b[(size_t)(t + 1) * 128 + v];
            av_n = ad_b[(size_t)(t + 1) * 128 + v];
        }
        if (tid < 64)       sw[tid]       = corr_b[(size_t)t * 64 + tid];
        else if (tid < 128) swn[tid - 64] = corr_b[(size_t)(t + 1) * 64 + (tid - 64)];
        __syncthreads();

        float prc = 0.f, prcn = 0.f;
#pragma unroll
        for (int i = 0; i < 32; i++) {
            float wc = sw[cg * 32 + i];
            float m  = fmaf(wc, av, M[i] * (1.f - wc * ev));
            M[i] = m;
            prc  = fmaf(wc, m, prc);
            prcn = fmaf(swn[cg * 32 + i], m, prcn);
        }
        if (cg == 0) { s_rc[v] = prc; s_rcn[v] = prcn; }
        __syncthreads();
        if (cg == 1) {
            rc_b [(size_t)t * 128 + v] = s_rc[v]  + prc;
            rcn_b[(size_t)t * 128 + v] = s_rcn[v] + prcn;
        }
        __syncthreads();
    }
}

__global__ void behmas_kernel(const float* __restrict__ rc, const float* __restrict__ rcn,
                              const float* __restrict__ qa,
                              float* __restrict__ beh, float* __restrict__ mas)
{
    int tok = blockIdx.x;
    int i   = threadIdx.x;
    int b   = tok / TM1;
    int t   = tok - b * TM1;
    size_t o = (size_t)tok * 256 + i;
    if (i < 128) {
        beh[o] = rc [(size_t)tok * 128 + i];
        mas[o] = rcn[(size_t)tok * 128 + i];
    } else {
        beh[o] = qa[(size_t)(b * T_ + t)     * 256 + (i - 128)];
        mas[o] = qa[(size_t)(b * T_ + t + 1) * 256 + (i - 128)];
    }
}

__global__ void pred_kernel(const float* __restrict__ hs, const float* __restrict__ Wo,
                            const float* __restrict__ bo, float* __restrict__ out, int ntok)
{
    int g    = blockIdx.x * blockDim.x + threadIdx.x;
    int w    = g >> 5;
    int lane = g & 31;
    if (w >= ntok) return;
    const float* h = hs + (size_t)w * 256;
    float s = 0.f;
#pragma unroll
    for (int j = 0; j < 8; j++) s = fmaf(h[lane + j * 32], Wo[lane + j * 32], s);
#pragma unroll
    for (int o = 16; o; o >>= 1) s += __shfl_xor_sync(0xffffffffu, s, o);
    if (lane == 0) out[w] = 1.f / (1.f + __expf(-(s + bo[0])));
}

// ---------------------------------------------------------------------------
// Launch
// ---------------------------------------------------------------------------
extern "C" void kernel_launch(void* const* d_in, const int* in_sizes, int n_in,
                              void* d_out, int out_size)
{
    (void)in_sizes; (void)n_in; (void)out_size;

    const int*   q_data     = (const int*)  d_in[0];
    const int*   a_data     = (const int*)  d_in[1];
    const float* q_embed    = (const float*)d_in[2];
    const float* a_embed    = (const float*)d_in[3];
    const float* key_matrix = (const float*)d_in[4];
    const float* value_init = (const float*)d_in[5];
    const float* Wk  = (const float*)d_in[6];   const float* bk  = (const float*)d_in[7];
    const float* We  = (const float*)d_in[8];   const float* be  = (const float*)d_in[9];
    const float* We2 = (const float*)d_in[10];  const float* be2 = (const float*)d_in[11];
    const float* Wa  = (const float*)d_in[12];  const float* ba  = (const float*)d_in[13];
    const float* Wa2 = (const float*)d_in[14];  const float* ba2 = (const float*)d_in[15];
    const float* Ws  = (const float*)d_in[16];  const float* bs  = (const float*)d_in[17];
    const float* Wo  = (const float*)d_in[18];  const float* bo  = (const float*)d_in[19];
    const float* Wsb = (const float*)d_in[20];  const float* bsb = (const float*)d_in[21];
    const float* Wob = (const float*)d_in[22];  const float* bob = (const float*)d_in[23];
    float* out = (float*)d_out;

    float *p_qa, *p_t1, *p_t2, *p_rk, *p_log, *p_corr, *p_er, *p_ad;
    float *p_rc, *p_rcn, *p_beh, *p_mas, *p_hb, *p_hs;
    __nv_bfloat16 *p_A3, *p_B3;
    cudaGetSymbolAddress((void**)&p_qa,   g_qa);
    cudaGetSymbolAddress((void**)&p_t1,   g_t1);
    cudaGetSymbolAddress((void**)&p_t2,   g_t2);
    cudaGetSymbolAddress((void**)&p_rk,   g_rk);
    cudaGetSymbolAddress((void**)&p_log,  g_logits);
    cudaGetSymbolAddress((void**)&p_corr, g_corr);
    cudaGetSymbolAddress((void**)&p_er,   g_erase);
    cudaGetSymbolAddress((void**)&p_ad,   g_add);
    cudaGetSymbolAddress((void**)&p_rc,   g_rc);
    cudaGetSymbolAddress((void**)&p_rcn,  g_rcn);
    cudaGetSymbolAddress((void**)&p_beh,  g_beh);
    cudaGetSymbolAddress((void**)&p_mas,  g_mas);
    cudaGetSymbolAddress((void**)&p_hb,   g_hb);
    cudaGetSymbolAddress((void**)&p_hs,   g_hs);
    cudaGetSymbolAddress((void**)&p_A3,   g_A3);
    cudaGetSymbolAddress((void**)&p_B3,   g_B3);

    const dim3 blk(256);

    // Independent of everything: split Wob to bf16 hi/lo
    convB_kernel<<<NPAD, 256>>>(Wob, p_B3);

    // Stage 0: gathers
    gather_kernel<<<NTOK, 256>>>(q_data, a_data, q_embed, a_embed, p_qa);

    // Stage A (fused): t1, t2, rk in one launch; er, ad in one launch
    gemm_fused3_kernel<<<dim3(1, NTOK / 128, 3), blk>>>(
        p_qa, We, be, Wa, ba, Wk, bk, p_t1, p_t2, p_rk);
    gemm_fused2_kernel<<<dim3(1, NTOK / 128, 2), blk>>>(
        p_t1, p_t2, We2, be2, Wa2, ba2, p_er, p_ad);
    gemm_nt_kernel<<<dim3(1, NTOK / 128), blk>>>(
        p_rk, 128, key_matrix, 128, nullptr, p_log, 64, NTOK, 64, 128, 0);
    softmax64_kernel<<<(NTOK * 32 + 255) / 256, 256>>>(p_log, p_corr, NTOK);

    // Stage B: sequential memory scan
    scan_kernel<<<B_, 256>>>(p_corr, p_er, p_ad, value_init, p_rc, p_rcn);

    // Stage C: readout
    behmas_kernel<<<NTOK1, 256>>>(p_rc, p_rcn, p_qa, p_beh, p_mas);
    gemm_nt_kernel<<<dim3(2, NTOK1 / 128), blk>>>(
        p_beh, 256, Wsb, 256, bsb, p_hb, 256, NTOK1, 256, 256, 2);

    // Split hb to bf16 hi/lo, then tensor-core big GEMM
    convA_kernel<<<NTOK1, 256>>>(p_hb, p_A3);
    mma_big_kernel<<<dim3(NPAD / 128, NTOK1 / 128), blk>>>(
        p_A3, p_B3, bob, out + NTOK1);

    // pred path
    gemm_nt_kernel<<<dim3(2, NTOK1 / 128), blk>>>(
        p_mas, 256, Ws, 256, bs, p_hs, 256, NTOK1, 256, 256, 2);
    pred_kernel<<<(NTOK1 * 32 + 255) / 256, 256>>>(p_hs, Wo, bo, out, NTOK1);
}

// round 8
// speedup vs baseline: 1.7797x; 1.0619x over previous
#include <cuda_runtime.h>
#include <cuda_bf16.h>
#include <math.h>

// Problem constants
#define B_   128
#define T_   200
#define TM1  199
#define NQP1 5001
#define NPAD 5120            // 5001 padded to 40*128 tiles
#define K3   768             // 3 * 256 (bf16 hi/lo split GEMM)
#define NTOK  (B_ * T_)      // 25600
#define NTOK1 (B_ * TM1)     // 25472

// ---------------------------------------------------------------------------
// Device scratch
// ---------------------------------------------------------------------------
__device__ __align__(16) float g_qa    [NTOK  * 256];
__device__ __align__(16) float g_t1    [NTOK  * 128];
__device__ __align__(16) float g_t2    [NTOK  * 128];
__device__ __align__(16) float g_rk    [NTOK  * 128];
__device__ __align__(16) float g_logits[NTOK  *  64];
__device__ __align__(16) float g_corr  [NTOK  *  64];
__device__ __align__(16) float g_erase [NTOK  * 128];
__device__ __align__(16) float g_add   [NTOK  * 128];
__device__ __align__(16) float g_rc    [NTOK1 * 128];
__device__ __align__(16) float g_rcn   [NTOK1 * 128];
__device__ __align__(16) float g_beh   [NTOK1 * 256];
__device__ __align__(16) float g_mas   [NTOK1 * 256];
__device__ __align__(16) float g_hs    [NTOK1 * 256];
__device__ __align__(16) __nv_bfloat16 g_A3[(size_t)NTOK1 * K3];  // tanh(beh@Wsb) split
__device__ __align__(16) __nv_bfloat16 g_B3[(size_t)NPAD  * K3];  // Wob split

// ---------------------------------------------------------------------------
// fp32 SIMT GEMM body: C[m,n] = act(sum_k A[m,k]*W[n,k] + bias[n])
// 128x128x8 tiles, 256 threads, 8x8 microtile. act: 0 none, 1 sigmoid, 2 tanh
// ---------------------------------------------------------------------------
__device__ __forceinline__ void gemm_accum(
    const float* __restrict__ A, int lda,
    const float* __restrict__ W, int ldw,
    int N, int K, int m0, int n0,
    float acc[8][8])
{
    __shared__ float As[8][132];
    __shared__ float Bs[8][132];

    const int tid = threadIdx.x;
    const int tx  = tid & 15;
    const int ty  = tid >> 4;
    const int lr  = tid >> 1;
    const int lc  = (tid & 1) << 2;

    const float* Ap = A + (size_t)(m0 + lr) * lda + lc;
    const int    wrow = n0 + lr;
    const float* Wp = W + (size_t)wrow * ldw + lc;
    const bool   wok = (wrow < N);

    for (int k0 = 0; k0 < K; k0 += 8) {
        float4 av = *reinterpret_cast<const float4*>(Ap + k0);
        float4 wv = wok ? *reinterpret_cast<const float4*>(Wp + k0)
                        : make_float4(0.f, 0.f, 0.f, 0.f);
        __syncthreads();
        As[lc + 0][lr] = av.x; As[lc + 1][lr] = av.y;
        As[lc + 2][lr] = av.z; As[lc + 3][lr] = av.w;
        Bs[lc + 0][lr] = wv.x; Bs[lc + 1][lr] = wv.y;
        Bs[lc + 2][lr] = wv.z; Bs[lc + 3][lr] = wv.w;
        __syncthreads();
#pragma unroll
        for (int kk = 0; kk < 8; kk++) {
            float4 a0 = *reinterpret_cast<const float4*>(&As[kk][ty * 8]);
            float4 a1 = *reinterpret_cast<const float4*>(&As[kk][ty * 8 + 4]);
            float4 b0 = *reinterpret_cast<const float4*>(&Bs[kk][tx * 8]);
            float4 b1 = *reinterpret_cast<const float4*>(&Bs[kk][tx * 8 + 4]);
            float a[8] = {a0.x, a0.y, a0.z, a0.w, a1.x, a1.y, a1.z, a1.w};
            float b[8] = {b0.x, b0.y, b0.z, b0.w, b1.x, b1.y, b1.z, b1.w};
#pragma unroll
            for (int i = 0; i < 8; i++)
#pragma unroll
                for (int j = 0; j < 8; j++)
                    acc[i][j] = fmaf(a[i], b[j], acc[i][j]);
        }
    }
}

__device__ __forceinline__ void gemm_body(
    const float* __restrict__ A, int lda,
    const float* __restrict__ W, int ldw,
    const float* __restrict__ bias,
    float* __restrict__ C, int ldc,
    int M, int N, int K, int act,
    int m0, int n0)
{
    const int tid = threadIdx.x;
    const int tx  = tid & 15;
    const int ty  = tid >> 4;

    float acc[8][8];
#pragma unroll
    for (int i = 0; i < 8; i++)
#pragma unroll
        for (int j = 0; j < 8; j++) acc[i][j] = 0.f;

    gemm_accum(A, lda, W, ldw, N, K, m0, n0, acc);

    float bb[8];
#pragma unroll
    for (int j = 0; j < 8; j++) {
        int n = n0 + tx * 8 + j;
        bb[j] = (bias != nullptr && n < N) ? bias[n] : 0.f;
    }
#pragma unroll
    for (int i = 0; i < 8; i++) {
        int m = m0 + ty * 8 + i;
        if (m >= M) continue;
#pragma unroll
        for (int j = 0; j < 8; j++) {
            int n = n0 + tx * 8 + j;
            if (n >= N) continue;
            float v = acc[i][j] + bb[j];
            if (act == 1) v = 1.f / (1.f + __expf(-v));
            else if (act == 2) v = tanhf(v);
            C[(size_t)m * ldc + n] = v;
        }
    }
}

__global__ void __launch_bounds__(256, 2) gemm_nt_kernel(
    const float* __restrict__ A, int lda,
    const float* __restrict__ W, int ldw,
    const float* __restrict__ bias,
    float* __restrict__ C, int ldc,
    int M, int N, int K, int act)
{
    gemm_body(A, lda, W, ldw, bias, C, ldc, M, N, K, act,
              blockIdx.y * 128, blockIdx.x * 128);
}

// Fused: z=0 -> t1 = qa@We.T+be (K=256, ldw=256)
//        z=1 -> t2 = qa@Wa.T+ba (K=256, ldw=256)
//        z=2 -> rk = qe@Wk.T+bk (K=128, ldw=128)
__global__ void __launch_bounds__(256, 2) gemm_fused3_kernel(
    const float* __restrict__ qa,
    const float* __restrict__ We, const float* __restrict__ be,
    const float* __restrict__ Wa, const float* __restrict__ ba,
    const float* __restrict__ Wk, const float* __restrict__ bk,
    float* __restrict__ t1, float* __restrict__ t2, float* __restrict__ rk)
{
    const float* W; const float* bias; float* C; int K; int ldw;
    if (blockIdx.z == 0)      { W = We; bias = be; C = t1; K = 256; ldw = 256; }
    else if (blockIdx.z == 1) { W = Wa; bias = ba; C = t2; K = 256; ldw = 256; }
    else                      { W = Wk; bias = bk; C = rk; K = 128; ldw = 128; }
    gemm_body(qa, 256, W, ldw, bias, C, 128, NTOK, 128, K, 0,
              blockIdx.y * 128, 0);
}

// Fused: z=0 -> er = sigmoid(t1@We2.T+be2); z=1 -> ad = tanh(t2@Wa2.T+ba2)
__global__ void __launch_bounds__(256, 2) gemm_fused2_kernel(
    const float* __restrict__ t1, const float* __restrict__ t2,
    const float* __restrict__ We2, const float* __restrict__ be2,
    const float* __restrict__ Wa2, const float* __restrict__ ba2,
    float* __restrict__ er, float* __restrict__ ad)
{
    const float* A; const float* W; const float* bias; float* C; int act;
    if (blockIdx.z == 0) { A = t1; W = We2; bias = be2; C = er; act = 1; }
    else                 { A = t2; W = Wa2; bias = ba2; C = ad; act = 2; }
    gemm_body(A, 128, W, 128, bias, C, 128, NTOK, 128, 128, act,
              blockIdx.y * 128, 0);
}

// ---------------------------------------------------------------------------
// Wsb GEMM with fused tanh + bf16 hi/lo split epilogue:
//   v = tanh(beh @ Wsb.T + bsb)   ->  A3 = [hi(v) | lo(v) | hi(v)] per row
// M=NTOK1, N=256, K=256. Grid (2, NTOK1/128).
// ---------------------------------------------------------------------------
__global__ void __launch_bounds__(256, 2) gemm_wsb_kernel(
    const float* __restrict__ A,
    const float* __restrict__ W, const float* __restrict__ bias,
    __nv_bfloat16* __restrict__ Y)
{
    const int m0 = blockIdx.y * 128;
    const int n0 = blockIdx.x * 128;
    const int tid = threadIdx.x;
    const int tx  = tid & 15;
    const int ty  = tid >> 4;

    float acc[8][8];
#pragma unroll
    for (int i = 0; i < 8; i++)
#pragma unroll
        for (int j = 0; j < 8; j++) acc[i][j] = 0.f;

    gemm_accum(A, 256, W, 256, 256, 256, m0, n0, acc);

    float bb[8];
#pragma unroll
    for (int j = 0; j < 8; j++) bb[j] = bias[n0 + tx * 8 + j];

#pragma unroll
    for (int i = 0; i < 8; i++) {
        const int m = m0 + ty * 8 + i;
        const int n = n0 + tx * 8;
        __nv_bfloat16 hv[8], lv[8];
#pragma unroll
        for (int j = 0; j < 8; j++) {
            float v = tanhf(acc[i][j] + bb[j]);
            __nv_bfloat16 h = __float2bfloat16(v);
            hv[j] = h;
            lv[j] = __float2bfloat16(v - __bfloat162float(h));
        }
        size_t base = (size_t)m * K3;
        *reinterpret_cast<uint4*>(&Y[base + n])       = *reinterpret_cast<uint4*>(hv);
        *reinterpret_cast<uint4*>(&Y[base + 256 + n]) = *reinterpret_cast<uint4*>(lv);
        *reinterpret_cast<uint4*>(&Y[base + 512 + n]) = *reinterpret_cast<uint4*>(hv);
    }
}

// B3 = [hi(Wob) | hi(Wob) | lo(Wob)]  (rows >= 5001 zeroed)
__global__ void convB_kernel(const float* __restrict__ X, __nv_bfloat16* __restrict__ Y)
{
    int idx = blockIdx.x * 256 + threadIdx.x;     // < NPAD*256
    int r = idx >> 8, c = idx & 255;
    float x = (r < NQP1) ? X[(size_t)r * 256 + c] : 0.f;
    __nv_bfloat16 h = __float2bfloat16(x);
    __nv_bfloat16 l = __float2bfloat16(x - __bfloat162float(h));
    size_t base = (size_t)r * K3;
    Y[base + c] = h; Y[base + 256 + c] = h; Y[base + 512 + c] = l;
}

// ---------------------------------------------------------------------------
// Big tensor-core GEMM: out = sigmoid(A3[M,768] @ B3[NPAD,768].T + bob)
// mma.sync.m16n8k16 bf16, CTA 128x128x32, 3-stage cp.async pipeline,
// XOR-swizzled smem (64B rows, conflict-free ldmatrix).
// 256 threads = 8 warps (2x4), warp tile 64x32.
// ---------------------------------------------------------------------------
__device__ __forceinline__ void mma16816(float c[4], const unsigned a[4],
                                         unsigned b0, unsigned b1)
{
    asm volatile(
        "mma.sync.aligned.m16n8k16.row.col.f32.bf16.bf16.f32 "
        "{%0,%1,%2,%3}, {%4,%5,%6,%7}, {%8,%9}, {%0,%1,%2,%3};\n"
        : "+f"(c[0]), "+f"(c[1]), "+f"(c[2]), "+f"(c[3])
        : "r"(a[0]), "r"(a[1]), "r"(a[2]), "r"(a[3]), "r"(b0), "r"(b1));
}

__device__ __forceinline__ unsigned saddr(const void* p)
{
    return (unsigned)__cvta_generic_to_shared(p);
}

__device__ __forceinline__ void cp16(unsigned d, const void* s)
{
    asm volatile("cp.async.cg.shared.global [%0], [%1], 16;\n" :: "r"(d), "l"(s));
}

// Swizzled byte offset of 16B chunk `c` (0..3) in row `row` of a [128][32]bf16
// tile (64B rows): chunk' = c ^ ((row>>1)&3). Conflict-free for 8-row ldmatrix
// phases AND for rows r, r+8 (verified by enumeration).
__device__ __forceinline__ unsigned sw16(int row, int c)
{
    return (unsigned)(row * 64 + (((c ^ (row >> 1)) & 3) << 4));
}

#define NST (K3 / 32)   // 24 K-stages

__global__ void __launch_bounds__(256, 2) mma_big_kernel(
    const __nv_bfloat16* __restrict__ A,   // [NTOK1][768]
    const __nv_bfloat16* __restrict__ Bm,  // [NPAD][768]
    const float* __restrict__ bias,        // bob [5001]
    float* __restrict__ C)                 // [NTOK1][5001]
{
    __shared__ __nv_bfloat16 As[3][128][32];   // 3-stage, 8KB each
    __shared__ __nv_bfloat16 Bs[3][128][32];   // total 48KB exactly

    const int tid  = threadIdx.x;
    const int lane = tid & 31, wid = tid >> 5;
    const int wm = wid & 1, wn = wid >> 1;       // warp grid 2(M) x 4(N)
    const int m0 = blockIdx.y * 128;
    const int n0 = blockIdx.x * 128;

    float acc[4][4][4];
#pragma unroll
    for (int mt = 0; mt < 4; mt++)
#pragma unroll
        for (int nt = 0; nt < 4; nt++)
#pragma unroll
            for (int r = 0; r < 4; r++) acc[mt][nt][r] = 0.f;

    const __nv_bfloat16* Ag = A  + (size_t)m0 * K3;
    const __nv_bfloat16* Bg = Bm + (size_t)n0 * K3;
    const int rr = tid >> 1;             // load row 0..127
    const int ch = (tid & 1) * 2;        // load chunks ch, ch+1 (16B each)

    // ldmatrix lane mapping
    const int lr8 = (lane & 7) + ((lane >> 3) & 1) * 8;   // row in 16-row tile
    const int cq  = lane >> 4;                            // chunk half (0/1)

    const unsigned ab0 = saddr(&As[0][0][0]);
    const unsigned bb0 = saddr(&Bs[0][0][0]);

#define LOAD_STAGE(buf, k0)                                              \
    do {                                                                 \
        const __nv_bfloat16* pa = Ag + (size_t)rr * K3 + (k0) + ch * 8;  \
        const __nv_bfloat16* pb = Bg + (size_t)rr * K3 + (k0) + ch * 8;  \
        unsigned ab = ab0 + (buf) * 8192;                                \
        unsigned bb = bb0 + (buf) * 8192;                                \
        cp16(ab + sw16(rr, ch),     pa);                                 \
        cp16(ab + sw16(rr, ch + 1), pa + 8);                             \
        cp16(bb + sw16(rr, ch),     pb);                                 \
        cp16(bb + sw16(rr, ch + 1), pb + 8);                             \
        asm volatile("cp.async.commit_group;\n");                        \
    } while (0)

    LOAD_STAGE(0, 0);
    LOAD_STAGE(1, 32);

    for (int st = 0; st < NST; st++) {
        if (st + 2 < NST) {
            LOAD_STAGE((st + 2) % 3, (st + 2) * 32);
            asm volatile("cp.async.wait_group 2;\n");
        } else if (st + 1 < NST) {
            asm volatile("cp.async.wait_group 1;\n");
        } else {
            asm volatile("cp.async.wait_group 0;\n");
        }
        __syncthreads();

        const int buf = st % 3;
        const unsigned ab = ab0 + buf * 8192;
        const unsigned bb = bb0 + buf * 8192;
#pragma unroll
        for (int ks = 0; ks < 2; ks++) {
            const int chv = ks * 2 + cq;    // this lane's 16B chunk index
            unsigned af[4][4], bq[4][2];
#pragma unroll
            for (int mt = 0; mt < 4; mt++) {
                unsigned ad = ab + sw16(wm * 64 + mt * 16 + lr8, chv);
                asm volatile(
                    "ldmatrix.sync.aligned.m8n8.x4.shared.b16 {%0,%1,%2,%3}, [%4];\n"
                    : "=r"(af[mt][0]), "=r"(af[mt][1]),
                      "=r"(af[mt][2]), "=r"(af[mt][3]) : "r"(ad));
            }
#pragma unroll
            for (int bh = 0; bh < 2; bh++) {
                unsigned r0, r1, r2, r3;
                unsigned ad = bb + sw16(wn * 32 + bh * 16 + lr8, chv);
                asm volatile(
                    "ldmatrix.sync.aligned.m8n8.x4.shared.b16 {%0,%1,%2,%3}, [%4];\n"
                    : "=r"(r0), "=r"(r1), "=r"(r2), "=r"(r3) : "r"(ad));
                bq[bh * 2 + 0][0] = r0; bq[bh * 2 + 0][1] = r2;
                bq[bh * 2 + 1][0] = r1; bq[bh * 2 + 1][1] = r3;
            }
#pragma unroll
            for (int mt = 0; mt < 4; mt++)
#pragma unroll
                for (int nt = 0; nt < 4; nt++)
                    mma16816(acc[mt][nt], af[mt], bq[nt][0], bq[nt][1]);
        }
        __syncthreads();
    }

    // --- epilogue: bias + sigmoid, guarded at N=5001 ---
    const int gidr = lane >> 2, tig = lane & 3;
#pragma unroll
    for (int nt = 0; nt < 4; nt++) {
        const int n = n0 + wn * 32 + nt * 8 + tig * 2;
        const bool ok0 = (n < NQP1), ok1 = (n + 1 < NQP1);
        const float bb0f = ok0 ? bias[n] : 0.f;
        const float bb1f = ok1 ? bias[n + 1] : 0.f;
#pragma unroll
        for (int mt = 0; mt < 4; mt++) {
            const int m = m0 + wm * 64 + mt * 16 + gidr;
            float* Cr0 = C + (size_t)m * NQP1;
            float* Cr1 = C + (size_t)(m + 8) * NQP1;
            if (ok0) {
                Cr0[n] = 1.f / (1.f + __expf(-(acc[mt][nt][0] + bb0f)));
                Cr1[n] = 1.f / (1.f + __expf(-(acc[mt][nt][2] + bb0f)));
            }
            if (ok1) {
                Cr0[n + 1] = 1.f / (1.f + __expf(-(acc[mt][nt][1] + bb1f)));
                Cr1[n + 1] = 1.f / (1.f + __expf(-(acc[mt][nt][3] + bb1f)));
            }
        }
    }
}

// ---------------------------------------------------------------------------
// Gather / softmax / scan / concat / pred (verified)
// ---------------------------------------------------------------------------
__global__ void gather_kernel(const int* __restrict__ q, const int* __restrict__ a,
                              const float* __restrict__ qe, const float* __restrict__ ae,
                              float* __restrict__ qa)
{
    int tok = blockIdx.x;
    int i   = threadIdx.x;
    int qi  = q[tok];
    int ai  = a[tok];
    float v = (i < 128) ? qe[(size_t)qi * 128 + i]
                        : ae[(size_t)ai * 128 + (i - 128)];
    qa[(size_t)tok * 256 + i] = v;
}

__global__ void softmax64_kernel(const float* __restrict__ lg, float* __restrict__ co,
                                 int ntok)
{
    int g    = blockIdx.x * blockDim.x + threadIdx.x;
    int w    = g >> 5;
    int lane = g & 31;
    if (w >= ntok) return;
    const float* L = lg + (size_t)w * 64;
    float v0 = L[lane], v1 = L[lane + 32];
    float mx = fmaxf(v0, v1);
#pragma unroll
    for (int o = 16; o; o >>= 1) mx = fmaxf(mx, __shfl_xor_sync(0xffffffffu, mx, o));
    float e0 = __expf(v0 - mx), e1 = __expf(v1 - mx);
    float s = e0 + e1;
#pragma unroll
    for (int o = 16; o; o >>= 1) s += __shfl_xor_sync(0xffffffffu, s, o);
    float inv = 1.f / s;
    co[(size_t)w * 64 + lane]      = e0 * inv;
    co[(size_t)w * 64 + lane + 32] = e1 * inv;
}

__global__ void __launch_bounds__(256) scan_kernel(
    const float* __restrict__ corr, const float* __restrict__ er,
    const float* __restrict__ ad,   const float* __restrict__ vinit,
    float* __restrict__ rc, float* __restrict__ rcn)
{
    int b   = blockIdx.x;
    int tid = threadIdx.x;
    int v   = tid & 127;
    int cg  = tid >> 7;

    float M[32];
#pragma unroll
    for (int i = 0; i < 32; i++) M[i] = vinit[(size_t)(cg * 32 + i) * 128 + v];

    __shared__ float sw[64], swn[64], s_rc[128], s_rcn[128];

    const float* corr_b = corr + (size_t)b * T_ * 64;
    const float* er_b   = er   + (size_t)b * T_ * 128;
    const float* ad_b   = ad   + (size_t)b * T_ * 128;
    float* rc_b  = rc  + (size_t)b * TM1 * 128;
    float* rcn_b = rcn + (size_t)b * TM1 * 128;

    float ev_n = er_b[v];
    float av_n = ad_b[v];

    for (int t = 0; t < TM1; t++) {
        float ev = ev_n, av = av_n;
        if (t + 1 < TM1) {
            ev_n = er_b[(size_t)(t + 1) * 128 + v];
            av_n = ad_b[(size_t)(t + 1) * 128 + v];
        }
        if (tid < 64)       sw[tid]       = corr_b[(size_t)t * 64 + tid];
        else if (tid < 128) swn[tid - 64] = corr_b[(size_t)(t + 1) * 64 + (tid - 64)];
        __syncthreads();

        float prc = 0.f, prcn = 0.f;
#pragma unroll
        for (int i = 0; i < 32; i++) {
            float wc = sw[cg * 32 + i];
            float m  = fmaf(wc, av, M[i] * (1.f - wc * ev));
            M[i] = m;
            prc  = fmaf(wc, m, prc);
            prcn = fmaf(swn[cg * 32 + i], m, prcn);
        }
        if (cg == 0) { s_rc[v] = prc; s_rcn[v] = prcn; }
        __syncthreads();
        if (cg == 1) {
            rc_b [(size_t)t * 128 + v] = s_rc[v]  + prc;
            rcn_b[(size_t)t * 128 + v] = s_rcn[v] + prcn;
        }
        __syncthreads();
    }
}

__global__ void behmas_kernel(const float* __restrict__ rc, const float* __restrict__ rcn,
                              const float* __restrict__ qa,
                              float* __restrict__ beh, float* __restrict__ mas)
{
    int tok = blockIdx.x;
    int i   = threadIdx.x;
    int b   = tok / TM1;
    int t   = tok - b * TM1;
    size_t o = (size_t)tok * 256 + i;
    if (i < 128) {
        beh[o] = rc [(size_t)tok * 128 + i];
        mas[o] = rcn[(size_t)tok * 128 + i];
    } else {
        beh[o] = qa[(size_t)(b * T_ + t)     * 256 + (i - 128)];
        mas[o] = qa[(size_t)(b * T_ + t + 1) * 256 + (i - 128)];
    }
}

__global__ void pred_kernel(const float* __restrict__ hs, const float* __restrict__ Wo,
                            const float* __restrict__ bo, float* __restrict__ out, int ntok)
{
    int g    = blockIdx.x * blockDim.x + threadIdx.x;
    int w    = g >> 5;
    int lane = g & 31;
    if (w >= ntok) return;
    const float* h = hs + (size_t)w * 256;
    float s = 0.f;
#pragma unroll
    for (int j = 0; j < 8; j++) s = fmaf(h[lane + j * 32], Wo[lane + j * 32], s);
#pragma unroll
    for (int o = 16; o; o >>= 1) s += __shfl_xor_sync(0xffffffffu, s, o);
    if (lane == 0) out[w] = 1.f / (1.f + __expf(-(s + bo[0])));
}

// ---------------------------------------------------------------------------
// Launch
// ---------------------------------------------------------------------------
extern "C" void kernel_launch(void* const* d_in, const int* in_sizes, int n_in,
                              void* d_out, int out_size)
{
    (void)in_sizes; (void)n_in; (void)out_size;

    const int*   q_data     = (const int*)  d_in[0];
    const int*   a_data     = (const int*)  d_in[1];
    const float* q_embed    = (const float*)d_in[2];
    const float* a_embed    = (const float*)d_in[3];
    const float* key_matrix = (const float*)d_in[4];
    const float* value_init = (const float*)d_in[5];
    const float* Wk  = (const float*)d_in[6];   const float* bk  = (const float*)d_in[7];
    const float* We  = (const float*)d_in[8];   const float* be  = (const float*)d_in[9];
    const float* We2 = (const float*)d_in[10];  const float* be2 = (const float*)d_in[11];
    const float* Wa  = (const float*)d_in[12];  const float* ba  = (const float*)d_in[13];
    const float* Wa2 = (const float*)d_in[14];  const float* ba2 = (const float*)d_in[15];
    const float* Ws  = (const float*)d_in[16];  const float* bs  = (const float*)d_in[17];
    const float* Wo  = (const float*)d_in[18];  const float* bo  = (const float*)d_in[19];
    const float* Wsb = (const float*)d_in[20];  const float* bsb = (const float*)d_in[21];
    const float* Wob = (const float*)d_in[22];  const float* bob = (const float*)d_in[23];
    float* out = (float*)d_out;

    float *p_qa, *p_t1, *p_t2, *p_rk, *p_log, *p_corr, *p_er, *p_ad;
    float *p_rc, *p_rcn, *p_beh, *p_mas, *p_hs;
    __nv_bfloat16 *p_A3, *p_B3;
    cudaGetSymbolAddress((void**)&p_qa,   g_qa);
    cudaGetSymbolAddress((void**)&p_t1,   g_t1);
    cudaGetSymbolAddress((void**)&p_t2,   g_t2);
    cudaGetSymbolAddress((void**)&p_rk,   g_rk);
    cudaGetSymbolAddress((void**)&p_log,  g_logits);
    cudaGetSymbolAddress((void**)&p_corr, g_corr);
    cudaGetSymbolAddress((void**)&p_er,   g_erase);
    cudaGetSymbolAddress((void**)&p_ad,   g_add);
    cudaGetSymbolAddress((void**)&p_rc,   g_rc);
    cudaGetSymbolAddress((void**)&p_rcn,  g_rcn);
    cudaGetSymbolAddress((void**)&p_beh,  g_beh);
    cudaGetSymbolAddress((void**)&p_mas,  g_mas);
    cudaGetSymbolAddress((void**)&p_hs,   g_hs);
    cudaGetSymbolAddress((void**)&p_A3,   g_A3);
    cudaGetSymbolAddress((void**)&p_B3,   g_B3);

    const dim3 blk(256);

    // Independent of everything: split Wob to bf16 hi/lo
    convB_kernel<<<NPAD, 256>>>(Wob, p_B3);

    // Stage 0: gathers
    gather_kernel<<<NTOK, 256>>>(q_data, a_data, q_embed, a_embed, p_qa);

    // Stage A (fused)
    gemm_fused3_kernel<<<dim3(1, NTOK / 128, 3), blk>>>(
        p_qa, We, be, Wa, ba, Wk, bk, p_t1, p_t2, p_rk);
    gemm_fused2_kernel<<<dim3(1, NTOK / 128, 2), blk>>>(
        p_t1, p_t2, We2, be2, Wa2, ba2, p_er, p_ad);
    gemm_nt_kernel<<<dim3(1, NTOK / 128), blk>>>(
        p_rk, 128, key_matrix, 128, nullptr, p_log, 64, NTOK, 64, 128, 0);
    softmax64_kernel<<<(NTOK * 32 + 255) / 256, 256>>>(p_log, p_corr, NTOK);

    // Stage B: sequential memory scan
    scan_kernel<<<B_, 256>>>(p_corr, p_er, p_ad, value_init, p_rc, p_rcn);

    // Stage C: readout
    behmas_kernel<<<NTOK1, 256>>>(p_rc, p_rcn, p_qa, p_beh, p_mas);

    // Wsb GEMM with fused tanh + bf16 split epilogue -> A3 directly
    gemm_wsb_kernel<<<dim3(2, NTOK1 / 128), blk>>>(p_beh, Wsb, bsb, p_A3);

    // Big tensor-core GEMM
    mma_big_kernel<<<dim3(NPAD / 128, NTOK1 / 128), blk>>>(
        p_A3, p_B3, bob, out + NTOK1);

    // pred path
    gemm_nt_kernel<<<dim3(2, NTOK1 / 128), blk>>>(
        p_mas, 256, Ws, 256, bs, p_hs, 256, NTOK1, 256, 256, 2);
    pred_kernel<<<(NTOK1 * 32 + 255) / 256, 256>>>(p_hs, Wo, bo, out, NTOK1);
}

// round 11
// speedup vs baseline: 2.1471x; 1.2065x over previous
#include <cuda_runtime.h>
#include <cuda_bf16.h>
#include <math.h>
#include <cstdint>

using u32 = unsigned int;
using u64 = unsigned long long;
typedef __nv_bfloat16 bf16;

// Problem constants
#define B_   128
#define T_   200
#define TM1  199
#define NQP1 5001
#define NPAD 5120
#define NTOK  (B_ * T_)    // 25600
#define NTOK1 (B_ * TM1)   // 25472

// ---------------------------------------------------------------------------
// Device scratch (bf16 split layouts: A-side = [hi|lo|hi], B-side = [hi|hi|lo])
// ---------------------------------------------------------------------------
__device__ __align__(16) bf16  g_qa3  [(size_t)NTOK  * 768];
__device__ __align__(16) bf16  g_qe3  [(size_t)NTOK  * 384];
__device__ __align__(16) bf16  g_t13  [(size_t)NTOK  * 384];
__device__ __align__(16) bf16  g_t23  [(size_t)NTOK  * 384];
__device__ __align__(16) bf16  g_rk3  [(size_t)NTOK  * 384];
__device__ __align__(16) float g_logits[NTOK  *  64];
__device__ __align__(16) float g_corr  [NTOK  *  64];
__device__ __align__(16) float g_erase [NTOK  * 128];
__device__ __align__(16) float g_add   [NTOK  * 128];
__device__ __align__(16) float g_rc    [NTOK1 * 128];
__device__ __align__(16) float g_rcn   [NTOK1 * 128];
__device__ __align__(16) bf16  g_beh3 [(size_t)NTOK1 * 768];
__device__ __align__(16) bf16  g_mas3 [(size_t)NTOK1 * 768];
__device__ __align__(16) float g_hs    [NTOK1 * 256];
__device__ __align__(16) bf16  g_A3   [(size_t)NTOK1 * 768];
__device__ __align__(16) bf16  g_B3   [(size_t)NPAD  * 768];
// split weights (B-side layout)
__device__ __align__(16) bf16  g_We3 [128 * 768];
__device__ __align__(16) bf16  g_Wa3 [128 * 768];
__device__ __align__(16) bf16  g_We23[128 * 384];
__device__ __align__(16) bf16  g_Wa23[128 * 384];
__device__ __align__(16) bf16  g_Wk3 [128 * 384];
__device__ __align__(16) bf16  g_key3[128 * 384];
__device__ __align__(16) bf16  g_Wsb3[256 * 768];
__device__ __align__(16) bf16  g_Ws3 [256 * 768];

// ---------------------------------------------------------------------------
// mma.sync helpers (verified rounds 7-8)
// ---------------------------------------------------------------------------
__device__ __forceinline__ void mma16816(float c[4], const u32 a[4],
                                         u32 b0, u32 b1)
{
    asm volatile(
        "mma.sync.aligned.m16n8k16.row.col.f32.bf16.bf16.f32 "
        "{%0,%1,%2,%3}, {%4,%5,%6,%7}, {%8,%9}, {%0,%1,%2,%3};\n"
        : "+f"(c[0]), "+f"(c[1]), "+f"(c[2]), "+f"(c[3])
        : "r"(a[0]), "r"(a[1]), "r"(a[2]), "r"(a[3]), "r"(b0), "r"(b1));
}
__device__ __forceinline__ u32 saddr(const void* p)
{
    return (u32)__cvta_generic_to_shared(p);
}
__device__ __forceinline__ void cp16(u32 d, const void* s)
{
    asm volatile("cp.async.cg.shared.global [%0], [%1], 16;\n" :: "r"(d), "l"(s));
}
// swizzled byte offset: 16B chunk c (0..3) in row of a [128][32]bf16 tile
__device__ __forceinline__ u32 sw16(int row, int c)
{
    return (u32)(row * 64 + (((c ^ (row >> 1)) & 3) << 4));
}
template<int ACT>
__device__ __forceinline__ float apply_act(float v)
{
    if (ACT == 1) return 1.f / (1.f + __expf(-v));
    if (ACT == 2) return tanhf(v);
    return v;
}

// ---------------------------------------------------------------------------
// Generic bf16 split GEMM on tensor cores.
//   C[m,n] = act( sum_k A[m,k]*B[n,k] + bias[n] )
// A: [M, NST*32] bf16 (A-side split rows), B: [Npad, NST*32] bf16 (B-side split)
// CTA tile 128x128, 256 threads (warp grid 2x4, warp tile 64x32),
// 3-stage cp.async pipeline, ONE sync per K-stage (loads issued after sync).
// EPI 0: fp32 store to Cf (ldc, guard n<N).
// EPI 1: bf16 hi/lo/hi split store to Cs, row stride 3*splitW.
// ---------------------------------------------------------------------------
template<int NST, int ACT, int EPI>
__global__ void __launch_bounds__(256, 2) mma_gen(
    const bf16* __restrict__ A,
    const bf16* __restrict__ Bm,
    const float* __restrict__ bias,
    float* __restrict__ Cf,
    bf16* __restrict__ Cs,
    int ldc, int N, int splitW)
{
    __shared__ bf16 As[3][128][32];   // 8KB per stage
    __shared__ bf16 Bs[3][128][32];   // total 48KB

    const int KW   = NST * 32;
    const int tid  = threadIdx.x;
    const int lane = tid & 31, wid = tid >> 5;
    const int wm = wid & 1, wn = wid >> 1;
    const int m0 = blockIdx.y * 128;
    const int n0 = blockIdx.x * 128;

    float acc[4][4][4];
#pragma unroll
    for (int mt = 0; mt < 4; mt++)
#pragma unroll
        for (int nt = 0; nt < 4; nt++)
#pragma unroll
            for (int r = 0; r < 4; r++) acc[mt][nt][r] = 0.f;

    const bf16* Ag = A  + (size_t)m0 * KW;
    const bf16* Bg = Bm + (size_t)n0 * KW;
    const int rr = tid >> 1;           // load row 0..127
    const int ch = (tid & 1) * 2;      // chunks ch, ch+1

    const int lr8 = (lane & 7) + ((lane >> 3) & 1) * 8;
    const int cq  = lane >> 4;

    const u32 ab0 = saddr(&As[0][0][0]);
    const u32 bb0 = saddr(&Bs[0][0][0]);

#define LOAD_ST(buf, k0)                                              \
    do {                                                              \
        const bf16* pa = Ag + (size_t)rr * KW + (k0) + ch * 8;        \
        const bf16* pb = Bg + (size_t)rr * KW + (k0) + ch * 8;        \
        u32 ab = ab0 + (buf) * 8192;                                  \
        u32 bb = bb0 + (buf) * 8192;                                  \
        cp16(ab + sw16(rr, ch),     pa);                              \
        cp16(ab + sw16(rr, ch + 1), pa + 8);                          \
        cp16(bb + sw16(rr, ch),     pb);                              \
        cp16(bb + sw16(rr, ch + 1), pb + 8);                          \
        asm volatile("cp.async.commit_group;\n");                     \
    } while (0)

    LOAD_ST(0, 0);
    LOAD_ST(1, 32);

    for (int st = 0; st < NST; st++) {
        if (st < NST - 1)
            asm volatile("cp.async.wait_group 1;\n");
        else
            asm volatile("cp.async.wait_group 0;\n");
        __syncthreads();
        if (st + 2 < NST)
            LOAD_ST((st + 2) % 3, (st + 2) * 32);

        const int buf = st % 3;
        const u32 ab = ab0 + buf * 8192;
        const u32 bb = bb0 + buf * 8192;
#pragma unroll
        for (int ks = 0; ks < 2; ks++) {
            const int chv = ks * 2 + cq;
            u32 af[4][4], bq[4][2];
#pragma unroll
            for (int mt = 0; mt < 4; mt++) {
                u32 ad = ab + sw16(wm * 64 + mt * 16 + lr8, chv);
                asm volatile(
                    "ldmatrix.sync.aligned.m8n8.x4.shared.b16 {%0,%1,%2,%3}, [%4];\n"
                    : "=r"(af[mt][0]), "=r"(af[mt][1]),
                      "=r"(af[mt][2]), "=r"(af[mt][3]) : "r"(ad));
            }
#pragma unroll
            for (int bh = 0; bh < 2; bh++) {
                u32 r0, r1, r2, r3;
                u32 ad = bb + sw16(wn * 32 + bh * 16 + lr8, chv);
                asm volatile(
                    "ldmatrix.sync.aligned.m8n8.x4.shared.b16 {%0,%1,%2,%3}, [%4];\n"
                    : "=r"(r0), "=r"(r1), "=r"(r2), "=r"(r3) : "r"(ad));
                bq[bh * 2 + 0][0] = r0; bq[bh * 2 + 0][1] = r2;
                bq[bh * 2 + 1][0] = r1; bq[bh * 2 + 1][1] = r3;
            }
#pragma unroll
            for (int mt = 0; mt < 4; mt++)
#pragma unroll
                for (int nt = 0; nt < 4; nt++)
                    mma16816(acc[mt][nt], af[mt], bq[nt][0], bq[nt][1]);
        }
    }

    // epilogue
    const int gidr = lane >> 2, tig = lane & 3;
#pragma unroll
    for (int nt = 0; nt < 4; nt++) {
        const int n = n0 + wn * 32 + nt * 8 + tig * 2;
        const bool ok0 = (n < N), ok1 = (n + 1 < N);
        const float bA = (bias != nullptr && ok0) ? bias[n] : 0.f;
        const float bB = (bias != nullptr && ok1) ? bias[n + 1] : 0.f;
#pragma unroll
        for (int mt = 0; mt < 4; mt++) {
            const int m = m0 + wm * 64 + mt * 16 + gidr;
            float v00 = apply_act<ACT>(acc[mt][nt][0] + bA);
            float v01 = apply_act<ACT>(acc[mt][nt][1] + bB);
            float v10 = apply_act<ACT>(acc[mt][nt][2] + bA);
            float v11 = apply_act<ACT>(acc[mt][nt][3] + bB);
            if (EPI == 0) {
                if (ok0) {
                    Cf[(size_t)m * ldc + n]       = v00;
                    Cf[(size_t)(m + 8) * ldc + n] = v10;
                }
                if (ok1) {
                    Cf[(size_t)m * ldc + n + 1]       = v01;
                    Cf[(size_t)(m + 8) * ldc + n + 1] = v11;
                }
            } else {
                if (ok1) {   // split sites have N even; write pairs
                    bf16 h00 = __float2bfloat16(v00);
                    bf16 h01 = __float2bfloat16(v01);
                    bf16 h10 = __float2bfloat16(v10);
                    bf16 h11 = __float2bfloat16(v11);
                    bf16 l00 = __float2bfloat16(v00 - __bfloat162float(h00));
                    bf16 l01 = __float2bfloat16(v01 - __bfloat162float(h01));
                    bf16 l10 = __float2bfloat16(v10 - __bfloat162float(h10));
                    bf16 l11 = __float2bfloat16(v11 - __bfloat162float(h11));
                    size_t b0 = (size_t)m * 3 * splitW;
                    size_t b1 = (size_t)(m + 8) * 3 * splitW;
                    __nv_bfloat162 H0; H0.x = h00; H0.y = h01;
                    __nv_bfloat162 L0; L0.x = l00; L0.y = l01;
                    __nv_bfloat162 H1; H1.x = h10; H1.y = h11;
                    __nv_bfloat162 L1; L1.x = l10; L1.y = l11;
                    *reinterpret_cast<__nv_bfloat162*>(&Cs[b0 + n])              = H0;
                    *reinterpret_cast<__nv_bfloat162*>(&Cs[b0 + splitW + n])     = L0;
                    *reinterpret_cast<__nv_bfloat162*>(&Cs[b0 + 2 * splitW + n]) = H0;
                    *reinterpret_cast<__nv_bfloat162*>(&Cs[b1 + n])              = H1;
                    *reinterpret_cast<__nv_bfloat162*>(&Cs[b1 + splitW + n])     = L1;
                    *reinterpret_cast<__nv_bfloat162*>(&Cs[b1 + 2 * splitW + n]) = H1;
                }
            }
        }
    }
#undef LOAD_ST
}

// ---------------------------------------------------------------------------
// Weight split (B-side [hi|hi|lo]); rows >= Nw zeroed. grid = Npad*K/256.
// ---------------------------------------------------------------------------
__global__ void convW_kernel(const float* __restrict__ X, bf16* __restrict__ Y,
                             int Nw, int K)
{
    int idx = blockIdx.x * 256 + threadIdx.x;
    int r = idx / K, c = idx - r * K;
    float x = (r < Nw) ? X[(size_t)r * K + c] : 0.f;
    bf16 h = __float2bfloat16(x);
    bf16 l = __float2bfloat16(x - __bfloat162float(h));
    size_t base = (size_t)r * 3 * K;
    Y[base + c] = h; Y[base + K + c] = h; Y[base + 2 * K + c] = l;
}

// ---------------------------------------------------------------------------
// Gather -> qa3 [25600,768] and qe3 [25600,384], A-side split
// ---------------------------------------------------------------------------
__global__ void gather3_kernel(const int* __restrict__ q, const int* __restrict__ a,
                               const float* __restrict__ qet, const float* __restrict__ aet,
                               bf16* __restrict__ qa3, bf16* __restrict__ qe3)
{
    int tok = blockIdx.x;
    int i   = threadIdx.x;
    float v = (i < 128) ? qet[(size_t)q[tok] * 128 + i]
                        : aet[(size_t)a[tok] * 128 + (i - 128)];
    bf16 h = __float2bfloat16(v);
    bf16 l = __float2bfloat16(v - __bfloat162float(h));
    size_t b7 = (size_t)tok * 768;
    qa3[b7 + i] = h; qa3[b7 + 256 + i] = l; qa3[b7 + 512 + i] = h;
    if (i < 128) {
        size_t b3 = (size_t)tok * 384;
        qe3[b3 + i] = h; qe3[b3 + 128 + i] = l; qe3[b3 + 256 + i] = h;
    }
}

// ---------------------------------------------------------------------------
// behavior/mastery concat -> A-side split beh3/mas3 [25472,768]
// ---------------------------------------------------------------------------
__global__ void behmas3_kernel(const float* __restrict__ rc, const float* __restrict__ rcn,
                               const bf16* __restrict__ qa3,
                               bf16* __restrict__ beh3, bf16* __restrict__ mas3)
{
    int tok = blockIdx.x;
    int i   = threadIdx.x;
    int b   = tok / TM1;
    int t   = tok - b * TM1;
    float vb, vm;
    if (i < 128) {
        vb = rc [(size_t)tok * 128 + i];
        vm = rcn[(size_t)tok * 128 + i];
    } else {
        int c = i - 128;
        size_t r0 = (size_t)(b * T_ + t) * 768;
        size_t r1 = (size_t)(b * T_ + t + 1) * 768;
        vb = __bfloat162float(qa3[r0 + c]) + __bfloat162float(qa3[r0 + 256 + c]);
        vm = __bfloat162float(qa3[r1 + c]) + __bfloat162float(qa3[r1 + 256 + c]);
    }
    bf16 hb = __float2bfloat16(vb);
    bf16 lb = __float2bfloat16(vb - __bfloat162float(hb));
    bf16 hm = __float2bfloat16(vm);
    bf16 lm = __float2bfloat16(vm - __bfloat162float(hm));
    size_t o = (size_t)tok * 768;
    beh3[o + i] = hb; beh3[o + 256 + i] = lb; beh3[o + 512 + i] = hb;
    mas3[o + i] = hm; mas3[o + 256 + i] = lm; mas3[o + 512 + i] = hm;
}

// ---------------------------------------------------------------------------
// softmax / scan / pred (verified, unchanged)
// ---------------------------------------------------------------------------
__global__ void softmax64_kernel(const float* __restrict__ lg, float* __restrict__ co,
                                 int ntok)
{
    int g    = blockIdx.x * blockDim.x + threadIdx.x;
    int w    = g >> 5;
    int lane = g & 31;
    if (w >= ntok) return;
    const float* L = lg + (size_t)w * 64;
    float v0 = L[lane], v1 = L[lane + 32];
    float mx = fmaxf(v0, v1);
#pragma unroll
    for (int o = 16; o; o >>= 1) mx = fmaxf(mx, __shfl_xor_sync(0xffffffffu, mx, o));
    float e0 = __expf(v0 - mx), e1 = __expf(v1 - mx);
    float s = e0 + e1;
#pragma unroll
    for (int o = 16; o; o >>= 1) s += __shfl_xor_sync(0xffffffffu, s, o);
    float inv = 1.f / s;
    co[(size_t)w * 64 + lane]      = e0 * inv;
    co[(size_t)w * 64 + lane + 32] = e1 * inv;
}

__global__ void __launch_bounds__(256) scan_kernel(
    const float* __restrict__ corr, const float* __restrict__ er,
    const float* __restrict__ ad,   const float* __restrict__ vinit,
    float* __restrict__ rc, float* __restrict__ rcn)
{
    int b   = blockIdx.x;
    int tid = threadIdx.x;
    int v   = tid & 127;
    int cg  = tid >> 7;

    float M[32];
#pragma unroll
    for (int i = 0; i < 32; i++) M[i] = vinit[(size_t)(cg * 32 + i) * 128 + v];

    __shared__ float sw[64], swn[64], s_rc[128], s_rcn[128];

    const float* corr_b = corr + (size_t)b * T_ * 64;
    const float* er_b   = er   + (size_t)b * T_ * 128;
    const float* ad_b   = ad   + (size_t)b * T_ * 128;
    float* rc_b  = rc  + (size_t)b * TM1 * 128;
    float* rcn_b = rcn + (size_t)b * TM1 * 128;

    float ev_n = er_b[v];
    float av_n = ad_b[v];

    for (int t = 0; t < TM1; t++) {
        float ev = ev_n, av = av_n;
        if (t + 1 < TM1) {
            ev_n = er_b[(size_t)(t + 1) * 128 + v];
            av_n = ad_b[(size_t)(t + 1) * 128 + v];
        }
        if (tid < 64)       sw[tid]       = corr_b[(size_t)t * 64 + tid];
        else if (tid < 128) swn[tid - 64] = corr_b[(size_t)(t + 1) * 64 + (tid - 64)];
        __syncthreads();

        float prc = 0.f, prcn = 0.f;
#pragma unroll
        for (int i = 0; i < 32; i++) {
            float wc = sw[cg * 32 + i];
            float m  = fmaf(wc, av, M[i] * (1.f - wc * ev));
            M[i] = m;
            prc  = fmaf(wc, m, prc);
            prcn = fmaf(swn[cg * 32 + i], m, prcn);
        }
        if (cg == 0) { s_rc[v] = prc; s_rcn[v] = prcn; }
        __syncthreads();
        if (cg == 1) {
            rc_b [(size_t)t * 128 + v] = s_rc[v]  + prc;
            rcn_b[(size_t)t * 128 + v] = s_rcn[v] + prcn;
        }
        __syncthreads();
    }
}

__global__ void pred_kernel(const float* __restrict__ hs, const float* __restrict__ Wo,
                            const float* __restrict__ bo, float* __restrict__ out, int ntok)
{
    int g    = blockIdx.x * blockDim.x + threadIdx.x;
    int w    = g >> 5;
    int lane = g & 31;
    if (w >= ntok) return;
    const float* h = hs + (size_t)w * 256;
    float s = 0.f;
#pragma unroll
    for (int j = 0; j < 8; j++) s = fmaf(h[lane + j * 32], Wo[lane + j * 32], s);
#pragma unroll
    for (int o = 16; o; o >>= 1) s += __shfl_xor_sync(0xffffffffu, s, o);
    if (lane == 0) out[w] = 1.f / (1.f + __expf(-(s + bo[0])));
}

// ---------------------------------------------------------------------------
// Launch
// ---------------------------------------------------------------------------
extern "C" void kernel_launch(void* const* d_in, const int* in_sizes, int n_in,
                              void* d_out, int out_size)
{
    (void)in_sizes; (void)n_in; (void)out_size;

    const int*   q_data     = (const int*)  d_in[0];
    const int*   a_data     = (const int*)  d_in[1];
    const float* q_embed    = (const float*)d_in[2];
    const float* a_embed    = (const float*)d_in[3];
    const float* key_matrix = (const float*)d_in[4];
    const float* value_init = (const float*)d_in[5];
    const float* Wk  = (const float*)d_in[6];   const float* bk  = (const float*)d_in[7];
    const float* We  = (const float*)d_in[8];   const float* be  = (const float*)d_in[9];
    const float* We2 = (const float*)d_in[10];  const float* be2 = (const float*)d_in[11];
    const float* Wa  = (const float*)d_in[12];  const float* ba  = (const float*)d_in[13];
    const float* Wa2 = (const float*)d_in[14];  const float* ba2 = (const float*)d_in[15];
    const float* Ws  = (const float*)d_in[16];  const float* bs  = (const float*)d_in[17];
    const float* Wo  = (const float*)d_in[18];  const float* bo  = (const float*)d_in[19];
    const float* Wsb = (const float*)d_in[20];  const float* bsb = (const float*)d_in[21];
    const float* Wob = (const float*)d_in[22];  const float* bob = (const float*)d_in[23];
    float* out = (float*)d_out;

    bf16 *p_qa3, *p_qe3, *p_t13, *p_t23, *p_rk3, *p_beh3, *p_mas3, *p_A3, *p_B3;
    bf16 *p_We3, *p_Wa3, *p_We23, *p_Wa23, *p_Wk3, *p_key3, *p_Wsb3, *p_Ws3;
    float *p_log, *p_corr, *p_er, *p_ad, *p_rc, *p_rcn, *p_hs;
    cudaGetSymbolAddress((void**)&p_qa3,  g_qa3);
    cudaGetSymbolAddress((void**)&p_qe3,  g_qe3);
    cudaGetSymbolAddress((void**)&p_t13,  g_t13);
    cudaGetSymbolAddress((void**)&p_t23,  g_t23);
    cudaGetSymbolAddress((void**)&p_rk3,  g_rk3);
    cudaGetSymbolAddress((void**)&p_log,  g_logits);
    cudaGetSymbolAddress((void**)&p_corr, g_corr);
    cudaGetSymbolAddress((void**)&p_er,   g_erase);
    cudaGetSymbolAddress((void**)&p_ad,   g_add);
    cudaGetSymbolAddress((void**)&p_rc,   g_rc);
    cudaGetSymbolAddress((void**)&p_rcn,  g_rcn);
    cudaGetSymbolAddress((void**)&p_beh3, g_beh3);
    cudaGetSymbolAddress((void**)&p_mas3, g_mas3);
    cudaGetSymbolAddress((void**)&p_hs,   g_hs);
    cudaGetSymbolAddress((void**)&p_A3,   g_A3);
    cudaGetSymbolAddress((void**)&p_B3,   g_B3);
    cudaGetSymbolAddress((void**)&p_We3,  g_We3);
    cudaGetSymbolAddress((void**)&p_Wa3,  g_Wa3);
    cudaGetSymbolAddress((void**)&p_We23, g_We23);
    cudaGetSymbolAddress((void**)&p_Wa23, g_Wa23);
    cudaGetSymbolAddress((void**)&p_Wk3,  g_Wk3);
    cudaGetSymbolAddress((void**)&p_key3, g_key3);
    cudaGetSymbolAddress((void**)&p_Wsb3, g_Wsb3);
    cudaGetSymbolAddress((void**)&p_Ws3,  g_Ws3);

    // ---- weight splits (independent of data) ----
    convW_kernel<<<128 * 256 / 256, 256>>>(We,  p_We3, 128, 256);
    convW_kernel<<<128 * 256 / 256, 256>>>(Wa,  p_Wa3, 128, 256);
    convW_kernel<<<128 * 128 / 256, 256>>>(We2, p_We23, 128, 128);
    convW_kernel<<<128 * 128 / 256, 256>>>(Wa2, p_Wa23, 128, 128);
    convW_kernel<<<128 * 128 / 256, 256>>>(Wk,  p_Wk3, 128, 128);
    convW_kernel<<<128 * 128 / 256, 256>>>(key_matrix, p_key3, 64, 128);
    convW_kernel<<<256 * 256 / 256, 256>>>(Wsb, p_Wsb3, 256, 256);
    convW_kernel<<<256 * 256 / 256, 256>>>(Ws,  p_Ws3, 256, 256);
    convW_kernel<<<NPAD * 256 / 256, 256>>>(Wob, p_B3, NQP1, 256);

    // ---- gather (writes split qa3, qe3) ----
    gather3_kernel<<<NTOK, 256>>>(q_data, a_data, q_embed, a_embed, p_qa3, p_qe3);

    // ---- stage A on tensor cores ----
    mma_gen<24, 0, 1><<<dim3(1, NTOK / 128), 256>>>(
        p_qa3, p_We3, be, nullptr, p_t13, 0, 128, 128);
    mma_gen<24, 0, 1><<<dim3(1, NTOK / 128), 256>>>(
        p_qa3, p_Wa3, ba, nullptr, p_t23, 0, 128, 128);
    mma_gen<12, 0, 1><<<dim3(1, NTOK / 128), 256>>>(
        p_qe3, p_Wk3, bk, nullptr, p_rk3, 0, 128, 128);
    mma_gen<12, 1, 0><<<dim3(1, NTOK / 128), 256>>>(
        p_t13, p_We23, be2, p_er, nullptr, 128, 128, 0);
    mma_gen<12, 2, 0><<<dim3(1, NTOK / 128), 256>>>(
        p_t23, p_Wa23, ba2, p_ad, nullptr, 128, 128, 0);
    mma_gen<12, 0, 0><<<dim3(1, NTOK / 128), 256>>>(
        p_rk3, p_key3, nullptr, p_log, nullptr, 64, 64, 0);
    softmax64_kernel<<<(NTOK * 32 + 255) / 256, 256>>>(p_log, p_corr, NTOK);

    // ---- stage B: sequential scan ----
    scan_kernel<<<B_, 256>>>(p_corr, p_er, p_ad, value_init, p_rc, p_rcn);

    // ---- stage C ----
    behmas3_kernel<<<NTOK1, 256>>>(p_rc, p_rcn, p_qa3, p_beh3, p_mas3);
    mma_gen<24, 2, 1><<<dim3(2, NTOK1 / 128), 256>>>(
        p_beh3, p_Wsb3, bsb, nullptr, p_A3, 0, 256, 256);
    mma_gen<24, 2, 0><<<dim3(2, NTOK1 / 128), 256>>>(
        p_mas3, p_Ws3, bs, p_hs, nullptr, 256, 256, 0);

    // ---- big GEMM ----
    mma_gen<24, 1, 0><<<dim3(NPAD / 128, NTOK1 / 128), 256>>>(
        p_A3, p_B3, bob, out + NTOK1, nullptr, NQP1, NQP1, 0);

    // ---- pred ----
    pred_kernel<<<(NTOK1 * 32 + 255) / 256, 256>>>(p_hs, Wo, bo, out, NTOK1);
}

// round 12
// speedup vs baseline: 2.7640x; 1.2873x over previous
#include <cuda_runtime.h>
#include <cuda_bf16.h>
#include <math.h>
#include <cstdint>

using u32 = unsigned int;
using u64 = unsigned long long;
typedef __nv_bfloat16 bf16;

// Problem constants
#define B_   128
#define T_   200
#define TM1  199
#define NQP1 5001
#define NPAD 5120
#define NTOK  (B_ * T_)    // 25600
#define NTOK1 (B_ * TM1)   // 25472

#define SMEM_BYTES 98304   // 3-stage x (16KB A + 16KB B)

// ---------------------------------------------------------------------------
// Device scratch (bf16 split layouts: A-side = [hi|lo|hi], B-side = [hi|hi|lo])
// ---------------------------------------------------------------------------
__device__ __align__(16) bf16  g_qa3  [(size_t)NTOK  * 768];
__device__ __align__(16) bf16  g_qe3  [(size_t)NTOK  * 384];
__device__ __align__(16) bf16  g_t13  [(size_t)NTOK  * 384];
__device__ __align__(16) bf16  g_t23  [(size_t)NTOK  * 384];
__device__ __align__(16) bf16  g_rk3  [(size_t)NTOK  * 384];
__device__ __align__(16) float g_logits[NTOK  *  64];
__device__ __align__(16) float g_corr  [NTOK  *  64];
__device__ __align__(16) float g_erase [NTOK  * 128];
__device__ __align__(16) float g_add   [NTOK  * 128];
__device__ __align__(16) float g_rc    [NTOK1 * 128];
__device__ __align__(16) float g_rcn   [NTOK1 * 128];
__device__ __align__(16) bf16  g_beh3 [(size_t)NTOK1 * 768];
__device__ __align__(16) bf16  g_mas3 [(size_t)NTOK1 * 768];
__device__ __align__(16) float g_hs    [NTOK1 * 256];
__device__ __align__(16) bf16  g_A3   [(size_t)NTOK1 * 768];
__device__ __align__(16) bf16  g_B3   [(size_t)NPAD  * 768];
// split weights (B-side layout)
__device__ __align__(16) bf16  g_We3 [128 * 768];
__device__ __align__(16) bf16  g_Wa3 [128 * 768];
__device__ __align__(16) bf16  g_We23[128 * 384];
__device__ __align__(16) bf16  g_Wa23[128 * 384];
__device__ __align__(16) bf16  g_Wk3 [128 * 384];
__device__ __align__(16) bf16  g_key3[128 * 384];
__device__ __align__(16) bf16  g_Wsb3[256 * 768];
__device__ __align__(16) bf16  g_Ws3 [256 * 768];

// ---------------------------------------------------------------------------
// mma.sync helpers (verified rounds 7-11)
// ---------------------------------------------------------------------------
__device__ __forceinline__ void mma16816(float c[4], const u32 a[4],
                                         u32 b0, u32 b1)
{
    asm volatile(
        "mma.sync.aligned.m16n8k16.row.col.f32.bf16.bf16.f32 "
        "{%0,%1,%2,%3}, {%4,%5,%6,%7}, {%8,%9}, {%0,%1,%2,%3};\n"
        : "+f"(c[0]), "+f"(c[1]), "+f"(c[2]), "+f"(c[3])
        : "r"(a[0]), "r"(a[1]), "r"(a[2]), "r"(a[3]), "r"(b0), "r"(b1));
}
__device__ __forceinline__ u32 saddr(const void* p)
{
    return (u32)__cvta_generic_to_shared(p);
}
__device__ __forceinline__ void cp16(u32 d, const void* s)
{
    asm volatile("cp.async.cg.shared.global [%0], [%1], 16;\n" :: "r"(d), "l"(s));
}
// SW128 swizzled byte offset: 16B chunk c (0..7) in row of a [128][64]bf16 tile
__device__ __forceinline__ u32 sw16(int row, int c)
{
    return (u32)(row * 128 + (((c ^ row) & 7) << 4));
}
__device__ __forceinline__ float act_f(float v, int ACT)
{
    if (ACT == 1) return 1.f / (1.f + __expf(-v));
    if (ACT == 2) return tanhf(v);
    return v;
}

// ---------------------------------------------------------------------------
// Generic bf16 split GEMM core.  C[m,n] = act(sum_k A[m,k]*B[n,k] + bias[n])
// A: [M, NST*64] (A-side split rows), B: [Npad, NST*64] (B-side split rows).
// CTA tile 128x128, 256 threads (warp grid 2x4, warp tile 64x32).
// 3-stage cp.async pipeline, K-chunk 64, one __syncthreads per stage.
// EPI 0: fp32 store (ldc, guard n<N).  EPI 1: bf16 [hi|lo|hi] split store.
// ---------------------------------------------------------------------------
struct GArgs {
    const bf16* A; const bf16* B; const float* bias;
    float* Cf; bf16* Cs;
    int ldc, N, splitW, NST, ACT, EPI;
};

__device__ __forceinline__ void mma_core(const GArgs ga, int m0, int n0)
{
    extern __shared__ bf16 smbuf[];
    const int NST = ga.NST;
    const int KW  = NST * 64;

    const int tid  = threadIdx.x;
    const int lane = tid & 31, wid = tid >> 5;
    const int wm = wid & 1, wn = wid >> 1;

    float acc[4][4][4];
#pragma unroll
    for (int mt = 0; mt < 4; mt++)
#pragma unroll
        for (int nt = 0; nt < 4; nt++)
#pragma unroll
            for (int r = 0; r < 4; r++) acc[mt][nt][r] = 0.f;

    const bf16* Ag = ga.A + (size_t)m0 * KW;
    const bf16* Bg = ga.B + (size_t)n0 * KW;
    // loads: 4 granules of A + 4 of B per thread per stage
    const int lrow = tid >> 1;            // base rows tid>>1 then +... (see map)
    (void)lrow;

    const int lr8 = (lane & 7) + ((lane >> 3) & 1) * 8;
    const int cq  = lane >> 4;

    const u32 ab0 = saddr(smbuf);             // A stages: +buf*16384
    const u32 bb0 = ab0 + 49152;              // B stages: +buf*16384

#define LOAD_ST64(buf, k0)                                            \
    do {                                                              \
        u32 ab = ab0 + (buf) * 16384;                                 \
        u32 bb = bb0 + (buf) * 16384;                                 \
        _Pragma("unroll")                                             \
        for (int i = 0; i < 4; i++) {                                 \
            int g = tid + i * 256;                                    \
            int row = g >> 3, c = g & 7;                              \
            cp16(ab + sw16(row, c), Ag + (size_t)row * KW + (k0) + c * 8); \
            cp16(bb + sw16(row, c), Bg + (size_t)row * KW + (k0) + c * 8); \
        }                                                             \
        asm volatile("cp.async.commit_group;\n");                     \
    } while (0)

    LOAD_ST64(0, 0);
    LOAD_ST64(1, 64);

    for (int st = 0; st < NST; st++) {
        if (st < NST - 1)
            asm volatile("cp.async.wait_group 1;\n");
        else
            asm volatile("cp.async.wait_group 0;\n");
        __syncthreads();
        if (st + 2 < NST)
            LOAD_ST64((st + 2) % 3, (st + 2) * 64);

        const int buf = st % 3;
        const u32 ab = ab0 + buf * 16384;
        const u32 bb = bb0 + buf * 16384;
#pragma unroll
        for (int ks = 0; ks < 4; ks++) {
            const int chv = ks * 2 + cq;
            u32 af[4][4], bq[4][2];
#pragma unroll
            for (int mt = 0; mt < 4; mt++) {
                u32 ad = ab + sw16(wm * 64 + mt * 16 + lr8, chv);
                asm volatile(
                    "ldmatrix.sync.aligned.m8n8.x4.shared.b16 {%0,%1,%2,%3}, [%4];\n"
                    : "=r"(af[mt][0]), "=r"(af[mt][1]),
                      "=r"(af[mt][2]), "=r"(af[mt][3]) : "r"(ad));
            }
#pragma unroll
            for (int bh = 0; bh < 2; bh++) {
                u32 r0, r1, r2, r3;
                u32 ad = bb + sw16(wn * 32 + bh * 16 + lr8, chv);
                asm volatile(
                    "ldmatrix.sync.aligned.m8n8.x4.shared.b16 {%0,%1,%2,%3}, [%4];\n"
                    : "=r"(r0), "=r"(r1), "=r"(r2), "=r"(r3) : "r"(ad));
                bq[bh * 2 + 0][0] = r0; bq[bh * 2 + 0][1] = r2;
                bq[bh * 2 + 1][0] = r1; bq[bh * 2 + 1][1] = r3;
            }
#pragma unroll
            for (int mt = 0; mt < 4; mt++)
#pragma unroll
                for (int nt = 0; nt < 4; nt++)
                    mma16816(acc[mt][nt], af[mt], bq[nt][0], bq[nt][1]);
        }
    }
#undef LOAD_ST64

    // epilogue
    const int gidr = lane >> 2, tig = lane & 3;
#pragma unroll
    for (int nt = 0; nt < 4; nt++) {
        const int n = n0 + wn * 32 + nt * 8 + tig * 2;
        const bool ok0 = (n < ga.N), ok1 = (n + 1 < ga.N);
        const float bA = (ga.bias != nullptr && ok0) ? ga.bias[n] : 0.f;
        const float bB = (ga.bias != nullptr && ok1) ? ga.bias[n + 1] : 0.f;
#pragma unroll
        for (int mt = 0; mt < 4; mt++) {
            const int m = m0 + wm * 64 + mt * 16 + gidr;
            float v00 = act_f(acc[mt][nt][0] + bA, ga.ACT);
            float v01 = act_f(acc[mt][nt][1] + bB, ga.ACT);
            float v10 = act_f(acc[mt][nt][2] + bA, ga.ACT);
            float v11 = act_f(acc[mt][nt][3] + bB, ga.ACT);
            if (ga.EPI == 0) {
                if (ok0) {
                    ga.Cf[(size_t)m * ga.ldc + n]       = v00;
                    ga.Cf[(size_t)(m + 8) * ga.ldc + n] = v10;
                }
                if (ok1) {
                    ga.Cf[(size_t)m * ga.ldc + n + 1]       = v01;
                    ga.Cf[(size_t)(m + 8) * ga.ldc + n + 1] = v11;
                }
            } else {
                if (ok1) {
                    bf16 h00 = __float2bfloat16(v00);
                    bf16 h01 = __float2bfloat16(v01);
                    bf16 h10 = __float2bfloat16(v10);
                    bf16 h11 = __float2bfloat16(v11);
                    bf16 l00 = __float2bfloat16(v00 - __bfloat162float(h00));
                    bf16 l01 = __float2bfloat16(v01 - __bfloat162float(h01));
                    bf16 l10 = __float2bfloat16(v10 - __bfloat162float(h10));
                    bf16 l11 = __float2bfloat16(v11 - __bfloat162float(h11));
                    size_t b0 = (size_t)m * 3 * ga.splitW;
                    size_t b1 = (size_t)(m + 8) * 3 * ga.splitW;
                    __nv_bfloat162 H0; H0.x = h00; H0.y = h01;
                    __nv_bfloat162 L0; L0.x = l00; L0.y = l01;
                    __nv_bfloat162 H1; H1.x = h10; H1.y = h11;
                    __nv_bfloat162 L1; L1.x = l10; L1.y = l11;
                    *reinterpret_cast<__nv_bfloat162*>(&ga.Cs[b0 + n])                 = H0;
                    *reinterpret_cast<__nv_bfloat162*>(&ga.Cs[b0 + ga.splitW + n])     = L0;
                    *reinterpret_cast<__nv_bfloat162*>(&ga.Cs[b0 + 2 * ga.splitW + n]) = H0;
                    *reinterpret_cast<__nv_bfloat162*>(&ga.Cs[b1 + n])                 = H1;
                    *reinterpret_cast<__nv_bfloat162*>(&ga.Cs[b1 + ga.splitW + n])     = L1;
                    *reinterpret_cast<__nv_bfloat162*>(&ga.Cs[b1 + 2 * ga.splitW + n]) = H1;
                }
            }
        }
    }
}

__global__ void __launch_bounds__(256, 2) mma_one(GArgs ga)
{
    mma_core(ga, blockIdx.y * 128, blockIdx.x * 128);
}

__global__ void __launch_bounds__(256, 2) mma_fused3(GArgs a0, GArgs a1, GArgs a2)
{
    GArgs ga = (blockIdx.z == 0) ? a0 : (blockIdx.z == 1) ? a1 : a2;
    mma_core(ga, blockIdx.y * 128, blockIdx.x * 128);
}

// ---------------------------------------------------------------------------
// Weight split (B-side [hi|hi|lo]); rows >= Nw zeroed. grid = Npad*K/256.
// ---------------------------------------------------------------------------
__global__ void convW_kernel(const float* __restrict__ X, bf16* __restrict__ Y,
                             int Nw, int K)
{
    int idx = blockIdx.x * 256 + threadIdx.x;
    int r = idx / K, c = idx - r * K;
    float x = (r < Nw) ? X[(size_t)r * K + c] : 0.f;
    bf16 h = __float2bfloat16(x);
    bf16 l = __float2bfloat16(x - __bfloat162float(h));
    size_t base = (size_t)r * 3 * K;
    Y[base + c] = h; Y[base + K + c] = h; Y[base + 2 * K + c] = l;
}

// ---------------------------------------------------------------------------
// Gather -> qa3 [25600,768] and qe3 [25600,384], A-side split
// ---------------------------------------------------------------------------
__global__ void gather3_kernel(const int* __restrict__ q, const int* __restrict__ a,
                               const float* __restrict__ qet, const float* __restrict__ aet,
                               bf16* __restrict__ qa3, bf16* __restrict__ qe3)
{
    int tok = blockIdx.x;
    int i   = threadIdx.x;
    float v = (i < 128) ? qet[(size_t)q[tok] * 128 + i]
                        : aet[(size_t)a[tok] * 128 + (i - 128)];
    bf16 h = __float2bfloat16(v);
    bf16 l = __float2bfloat16(v - __bfloat162float(h));
    size_t b7 = (size_t)tok * 768;
    qa3[b7 + i] = h; qa3[b7 + 256 + i] = l; qa3[b7 + 512 + i] = h;
    if (i < 128) {
        size_t b3 = (size_t)tok * 384;
        qe3[b3 + i] = h; qe3[b3 + 128 + i] = l; qe3[b3 + 256 + i] = h;
    }
}

// ---------------------------------------------------------------------------
// behavior/mastery concat -> A-side split beh3/mas3 [25472,768]
// ---------------------------------------------------------------------------
__global__ void behmas3_kernel(const float* __restrict__ rc, const float* __restrict__ rcn,
                               const bf16* __restrict__ qa3,
                               bf16* __restrict__ beh3, bf16* __restrict__ mas3)
{
    int tok = blockIdx.x;
    int i   = threadIdx.x;
    int b   = tok / TM1;
    int t   = tok - b * TM1;
    float vb, vm;
    if (i < 128) {
        vb = rc [(size_t)tok * 128 + i];
        vm = rcn[(size_t)tok * 128 + i];
    } else {
        int c = i - 128;
        size_t r0 = (size_t)(b * T_ + t) * 768;
        size_t r1 = (size_t)(b * T_ + t + 1) * 768;
        vb = __bfloat162float(qa3[r0 + c]) + __bfloat162float(qa3[r0 + 256 + c]);
        vm = __bfloat162float(qa3[r1 + c]) + __bfloat162float(qa3[r1 + 256 + c]);
    }
    bf16 hb = __float2bfloat16(vb);
    bf16 lb = __float2bfloat16(vb - __bfloat162float(hb));
    bf16 hm = __float2bfloat16(vm);
    bf16 lm = __float2bfloat16(vm - __bfloat162float(hm));
    size_t o = (size_t)tok * 768;
    beh3[o + i] = hb; beh3[o + 256 + i] = lb; beh3[o + 512 + i] = hb;
    mas3[o + i] = hm; mas3[o + 256 + i] = lm; mas3[o + 512 + i] = hm;
}

// ---------------------------------------------------------------------------
// softmax / scan / pred (verified, unchanged)
// ---------------------------------------------------------------------------
__global__ void softmax64_kernel(const float* __restrict__ lg, float* __restrict__ co,
                                 int ntok)
{
    int g    = blockIdx.x * blockDim.x + threadIdx.x;
    int w    = g >> 5;
    int lane = g & 31;
    if (w >= ntok) return;
    const float* L = lg + (size_t)w * 64;
    float v0 = L[lane], v1 = L[lane + 32];
    float mx = fmaxf(v0, v1);
#pragma unroll
    for (int o = 16; o; o >>= 1) mx = fmaxf(mx, __shfl_xor_sync(0xffffffffu, mx, o));
    float e0 = __expf(v0 - mx), e1 = __expf(v1 - mx);
    float s = e0 + e1;
#pragma unroll
    for (int o = 16; o; o >>= 1) s += __shfl_xor_sync(0xffffffffu, s, o);
    float inv = 1.f / s;
    co[(size_t)w * 64 + lane]      = e0 * inv;
    co[(size_t)w * 64 + lane + 32] = e1 * inv;
}

__global__ void __launch_bounds__(256) scan_kernel(
    const float* __restrict__ corr, const float* __restrict__ er,
    const float* __restrict__ ad,   const float* __restrict__ vinit,
    float* __restrict__ rc, float* __restrict__ rcn)
{
    int b   = blockIdx.x;
    int tid = threadIdx.x;
    int v   = tid & 127;
    int cg  = tid >> 7;

    float M[32];
#pragma unroll
    for (int i = 0; i < 32; i++) M[i] = vinit[(size_t)(cg * 32 + i) * 128 + v];

    __shared__ float sw[64], swn[64], s_rc[128], s_rcn[128];

    const float* corr_b = corr + (size_t)b * T_ * 64;
    const float* er_b   = er   + (size_t)b * T_ * 128;
    const float* ad_b   = ad   + (size_t)b * T_ * 128;
    float* rc_b  = rc  + (size_t)b * TM1 * 128;
    float* rcn_b = rcn + (size_t)b * TM1 * 128;

    float ev_n = er_b[v];
    float av_n = ad_b[v];

    for (int t = 0; t < TM1; t++) {
        float ev = ev_n, av = av_n;
        if (t + 1 < TM1) {
            ev_n = er_b[(size_t)(t + 1) * 128 + v];
            av_n = ad_b[(size_t)(t + 1) * 128 + v];
        }
        if (tid < 64)       sw[tid]       = corr_b[(size_t)t * 64 + tid];
        else if (tid < 128) swn[tid - 64] = corr_b[(size_t)(t + 1) * 64 + (tid - 64)];
        __syncthreads();

        float prc = 0.f, prcn = 0.f;
#pragma unroll
        for (int i = 0; i < 32; i++) {
            float wc = sw[cg * 32 + i];
            float m  = fmaf(wc, av, M[i] * (1.f - wc * ev));
            M[i] = m;
            prc  = fmaf(wc, m, prc);
            prcn = fmaf(swn[cg * 32 + i], m, prcn);
        }
        if (cg == 0) { s_rc[v] = prc; s_rcn[v] = prcn; }
        __syncthreads();
        if (cg == 1) {
            rc_b [(size_t)t * 128 + v] = s_rc[v]  + prc;
            rcn_b[(size_t)t * 128 + v] = s_rcn[v] + prcn;
        }
        __syncthreads();
    }
}

__global__ void pred_kernel(const float* __restrict__ hs, const float* __restrict__ Wo,
                            const float* __restrict__ bo, float* __restrict__ out, int ntok)
{
    int g    = blockIdx.x * blockDim.x + threadIdx.x;
    int w    = g >> 5;
    int lane = g & 31;
    if (w >= ntok) return;
    const float* h = hs + (size_t)w * 256;
    float s = 0.f;
#pragma unroll
    for (int j = 0; j < 8; j++) s = fmaf(h[lane + j * 32], Wo[lane + j * 32], s);
#pragma unroll
    for (int o = 16; o; o >>= 1) s += __shfl_xor_sync(0xffffffffu, s, o);
    if (lane == 0) out[w] = 1.f / (1.f + __expf(-(s + bo[0])));
}

// ---------------------------------------------------------------------------
// Launch
// ---------------------------------------------------------------------------
extern "C" void kernel_launch(void* const* d_in, const int* in_sizes, int n_in,
                              void* d_out, int out_size)
{
    (void)in_sizes; (void)n_in; (void)out_size;

    const int*   q_data     = (const int*)  d_in[0];
    const int*   a_data     = (const int*)  d_in[1];
    const float* q_embed    = (const float*)d_in[2];
    const float* a_embed    = (const float*)d_in[3];
    const float* key_matrix = (const float*)d_in[4];
    const float* value_init = (const float*)d_in[5];
    const float* Wk  = (const float*)d_in[6];   const float* bk  = (const float*)d_in[7];
    const float* We  = (const float*)d_in[8];   const float* be  = (const float*)d_in[9];
    const float* We2 = (const float*)d_in[10];  const float* be2 = (const float*)d_in[11];
    const float* Wa  = (const float*)d_in[12];  const float* ba  = (const float*)d_in[13];
    const float* Wa2 = (const float*)d_in[14];  const float* ba2 = (const float*)d_in[15];
    const float* Ws  = (const float*)d_in[16];  const float* bs  = (const float*)d_in[17];
    const float* Wo  = (const float*)d_in[18];  const float* bo  = (const float*)d_in[19];
    const float* Wsb = (const float*)d_in[20];  const float* bsb = (const float*)d_in[21];
    const float* Wob = (const float*)d_in[22];  const float* bob = (const float*)d_in[23];
    float* out = (float*)d_out;

    bf16 *p_qa3, *p_qe3, *p_t13, *p_t23, *p_rk3, *p_beh3, *p_mas3, *p_A3, *p_B3;
    bf16 *p_We3, *p_Wa3, *p_We23, *p_Wa23, *p_Wk3, *p_key3, *p_Wsb3, *p_Ws3;
    float *p_log, *p_corr, *p_er, *p_ad, *p_rc, *p_rcn, *p_hs;
    cudaGetSymbolAddress((void**)&p_qa3,  g_qa3);
    cudaGetSymbolAddress((void**)&p_qe3,  g_qe3);
    cudaGetSymbolAddress((void**)&p_t13,  g_t13);
    cudaGetSymbolAddress((void**)&p_t23,  g_t23);
    cudaGetSymbolAddress((void**)&p_rk3,  g_rk3);
    cudaGetSymbolAddress((void**)&p_log,  g_logits);
    cudaGetSymbolAddress((void**)&p_corr, g_corr);
    cudaGetSymbolAddress((void**)&p_er,   g_erase);
    cudaGetSymbolAddress((void**)&p_ad,   g_add);
    cudaGetSymbolAddress((void**)&p_rc,   g_rc);
    cudaGetSymbolAddress((void**)&p_rcn,  g_rcn);
    cudaGetSymbolAddress((void**)&p_beh3, g_beh3);
    cudaGetSymbolAddress((void**)&p_mas3, g_mas3);
    cudaGetSymbolAddress((void**)&p_hs,   g_hs);
    cudaGetSymbolAddress((void**)&p_A3,   g_A3);
    cudaGetSymbolAddress((void**)&p_B3,   g_B3);
    cudaGetSymbolAddress((void**)&p_We3,  g_We3);
    cudaGetSymbolAddress((void**)&p_Wa3,  g_Wa3);
    cudaGetSymbolAddress((void**)&p_We23, g_We23);
    cudaGetSymbolAddress((void**)&p_Wa23, g_Wa23);
    cudaGetSymbolAddress((void**)&p_Wk3,  g_Wk3);
    cudaGetSymbolAddress((void**)&p_key3, g_key3);
    cudaGetSymbolAddress((void**)&p_Wsb3, g_Wsb3);
    cudaGetSymbolAddress((void**)&p_Ws3,  g_Ws3);

    cudaFuncSetAttribute(mma_one,    cudaFuncAttributeMaxDynamicSharedMemorySize, SMEM_BYTES);
    cudaFuncSetAttribute(mma_fused3, cudaFuncAttributeMaxDynamicSharedMemorySize, SMEM_BYTES);

    // ---- weight splits ----
    convW_kernel<<<128 * 256 / 256, 256>>>(We,  p_We3, 128, 256);
    convW_kernel<<<128 * 256 / 256, 256>>>(Wa,  p_Wa3, 128, 256);
    convW_kernel<<<128 * 128 / 256, 256>>>(We2, p_We23, 128, 128);
    convW_kernel<<<128 * 128 / 256, 256>>>(Wa2, p_Wa23, 128, 128);
    convW_kernel<<<128 * 128 / 256, 256>>>(Wk,  p_Wk3, 128, 128);
    convW_kernel<<<128 * 128 / 256, 256>>>(key_matrix, p_key3, 64, 128);
    convW_kernel<<<256 * 256 / 256, 256>>>(Wsb, p_Wsb3, 256, 256);
    convW_kernel<<<256 * 256 / 256, 256>>>(Ws,  p_Ws3, 256, 256);
    convW_kernel<<<NPAD * 256 / 256, 256>>>(Wob, p_B3, NQP1, 256);

    // ---- gather ----
    gather3_kernel<<<NTOK, 256>>>(q_data, a_data, q_embed, a_embed, p_qa3, p_qe3);

    // ---- stage A: t1 | t2 | rk in one launch ----
    {
        GArgs a0 = { p_qa3, p_We3, be, nullptr, p_t13, 0, 128, 128, 12, 0, 1 };
        GArgs a1 = { p_qa3, p_Wa3, ba, nullptr, p_t23, 0, 128, 128, 12, 0, 1 };
        GArgs a2 = { p_qe3, p_Wk3, bk, nullptr, p_rk3, 0, 128, 128,  6, 0, 1 };
        mma_fused3<<<dim3(1, NTOK / 128, 3), 256, SMEM_BYTES>>>(a0, a1, a2);
    }
    // ---- stage A: er | ad | logits in one launch ----
    {
        GArgs a0 = { p_t13, p_We23, be2, p_er,  nullptr, 128, 128, 0, 6, 1, 0 };
        GArgs a1 = { p_t23, p_Wa23, ba2, p_ad,  nullptr, 128, 128, 0, 6, 2, 0 };
        GArgs a2 = { p_rk3, p_key3, nullptr, p_log, nullptr, 64, 64, 0, 6, 0, 0 };
        mma_fused3<<<dim3(1, NTOK / 128, 3), 256, SMEM_BYTES>>>(a0, a1, a2);
    }
    softmax64_kernel<<<(NTOK * 32 + 255) / 256, 256>>>(p_log, p_corr, NTOK);

    // ---- stage B: sequential scan ----
    scan_kernel<<<B_, 256>>>(p_corr, p_er, p_ad, value_init, p_rc, p_rcn);

    // ---- stage C ----
    behmas3_kernel<<<NTOK1, 256>>>(p_rc, p_rcn, p_qa3, p_beh3, p_mas3);
    {
        GArgs a0 = { p_beh3, p_Wsb3, bsb, nullptr, p_A3, 0, 256, 256, 12, 2, 1 };
        GArgs a1 = { p_mas3, p_Ws3,  bs,  p_hs,  nullptr, 256, 256, 0, 12, 2, 0 };
        mma_fused3<<<dim3(2, NTOK1 / 128, 2), 256, SMEM_BYTES>>>(a0, a1, a1);
    }
    pred_kernel<<<(NTOK1 * 32 + 255) / 256, 256>>>(p_hs, Wo, bo, out, NTOK1);

    // ---- big GEMM last (longest, nothing serialized behind it) ----
    {
        GArgs ab = { p_A3, p_B3, bob, out + NTOK1, nullptr, NQP1, NQP1, 0, 12, 1, 0 };
        mma_one<<<dim3(NPAD / 128, NTOK1 / 128), 256, SMEM_BYTES>>>(ab);
    }
}